// round 7
// baseline (speedup 1.0000x reference)
#include <cuda_runtime.h>
#include <stdint.h>
#include <math.h>

#define BB 2
#define HH 16
#define SS 2048
#define DD 1024
#define DH 64
#define MROWS (BB*SS)          // 4096
#define NROWS_TOT (BB*HH*SS)   // 65536 attn rows

static const size_t OUT_ELEMS  = (size_t)BB * SS * DD;        // 4,194,304
static const size_t ATTN_ELEMS = (size_t)BB * HH * SS * SS;   // 134,217,728

// Scratch (__device__ globals; allocation in kernel_launch is forbidden)
__device__ uint32_t g_qt[MROWS * DD];
__device__ uint32_t g_kt[MROWS * DD];
__device__ uint32_t g_vt[MROWS * DD];
__device__ uint32_t g_wqt[DD * DD];
__device__ uint32_t g_wkt[DD * DD];
__device__ uint32_t g_wvt[DD * DD];
__device__ uint32_t g_wot[DD * DD];
__device__ uint32_t g_qp[MROWS * DD];
__device__ uint32_t g_kp[MROWS * DD];
__device__ uint32_t g_vp[MROWS * DD];
__device__ uint32_t g_ctx[MROWS * DD];
__device__ float g_attn_fb[(size_t)BB * HH * SS * SS];
__device__ float g_part_l[(size_t)NROWS_TOT * 64];   // 64 partials per row

// ---------------------------------------------------------------------------
__device__ __forceinline__ uint32_t f2tf(float f) {
    uint32_t u;
    asm("cvt.rna.tf32.f32 %0, %1;" : "=r"(u) : "f"(f));
    return u;
}

__device__ __forceinline__ void mma_tf32(float c[4], const uint32_t a[4],
                                         const uint32_t b[2]) {
    asm volatile(
        "mma.sync.aligned.m16n8k8.row.col.f32.tf32.tf32.f32 "
        "{%0,%1,%2,%3}, {%4,%5,%6,%7}, {%8,%9}, {%0,%1,%2,%3};\n"
        : "+f"(c[0]), "+f"(c[1]), "+f"(c[2]), "+f"(c[3])
        : "r"(a[0]), "r"(a[1]), "r"(a[2]), "r"(a[3]), "r"(b[0]), "r"(b[1]));
}

__device__ __forceinline__ uint32_t smaddr(const void* p) {
    return (uint32_t)__cvta_generic_to_shared(p);
}
#define CP_ASYNC16(dst, src) \
    asm volatile("cp.async.cg.shared.global [%0], [%1], 16;" :: "r"(dst), "l"(src))
#define CP_COMMIT() asm volatile("cp.async.commit_group;")
#define CP_WAIT(n)  asm volatile("cp.async.wait_group %0;" :: "n"(n))

// ---------------------------------------------------------------------------
// One fused f32 -> tf32 conversion over all 7 tensors (grid-stride).
// ---------------------------------------------------------------------------
__global__ __launch_bounds__(256) void conv_all(
    const float4* __restrict__ q, const float4* __restrict__ k,
    const float4* __restrict__ v,
    const float4* __restrict__ wq, const float4* __restrict__ wk,
    const float4* __restrict__ wv, const float4* __restrict__ wo,
    uint4* __restrict__ qt, uint4* __restrict__ kt, uint4* __restrict__ vt,
    uint4* __restrict__ wqt, uint4* __restrict__ wkt, uint4* __restrict__ wvt,
    uint4* __restrict__ wot)
{
    const int NQ = MROWS * DD / 4;   // 1048576 (pow2)
    const int NW = DD * DD / 4;      // 262144  (pow2)
    const int TOT = 3 * NQ + 4 * NW;
    for (int i = blockIdx.x * 256 + threadIdx.x; i < TOT; i += gridDim.x * 256) {
        const float4* src; uint4* dst; int off;
        if (i < 3 * NQ) {
            int s = i >> 20;
            off = i & (NQ - 1);
            src = (s == 0) ? q : (s == 1) ? k : v;
            dst = (s == 0) ? qt : (s == 1) ? kt : vt;
        } else {
            int j = i - 3 * NQ;
            int s = j >> 18;
            off = j & (NW - 1);
            src = (s == 0) ? wq : (s == 1) ? wk : (s == 2) ? wv : wo;
            dst = (s == 0) ? wqt : (s == 1) ? wkt : (s == 2) ? wvt : wot;
        }
        float4 x = src[off];
        uint4 u = {f2tf(x.x), f2tf(x.y), f2tf(x.z), f2tf(x.w)};
        dst[off] = u;
    }
}

// ---------------------------------------------------------------------------
// Async GEMM core: C[4096,1024] = A @ W + bias (tf32-bit operands).
// Block 128x128, BK=32, 2-stage cp.async. Dynamic smem 71680 B.
// ---------------------------------------------------------------------------
template <bool TF32OUT>
__device__ __forceinline__ void gemm_async_core(
    const uint32_t* __restrict__ A, const uint32_t* __restrict__ W,
    const float* __restrict__ bias, void* __restrict__ Cout)
{
    extern __shared__ uint32_t dyn[];
    const int STG = 128 * 36 + 32 * 136;

    const int tid = threadIdx.x;
    const int lane = tid & 31;
    const int warp = tid >> 5;
    const int g = lane >> 2, t4 = lane & 3;
    const int warpM = warp >> 2, warpN = warp & 3;
    const int rowBase = blockIdx.y * 128;
    const int colBase = blockIdx.x * 128;
    const int mOff = warpM * 64, nOff = warpN * 32;

    const int ar = tid >> 3, ak = (tid & 7) * 4;
    auto prefetch = [&](int k0, int s) {
        uint32_t* As = dyn + s * STG;
        uint32_t* Ws = dyn + s * STG + 128 * 36;
#pragma unroll
        for (int i = 0; i < 4; i++) {
            int r = ar + i * 32;
            CP_ASYNC16(smaddr(&As[r * 36 + ak]),
                       A + (size_t)(rowBase + r) * DD + k0 + ak);
        }
#pragma unroll
        for (int i = 0; i < 4; i++) {
            int l = tid + i * 256;
            int r = l >> 5, nc = (l & 31) * 4;
            CP_ASYNC16(smaddr(&Ws[r * 136 + nc]),
                       W + (size_t)(k0 + r) * DD + colBase + nc);
        }
    };

    float acc[4][4][4];
#pragma unroll
    for (int m = 0; m < 4; m++)
#pragma unroll
        for (int n = 0; n < 4; n++)
#pragma unroll
            for (int i = 0; i < 4; i++) acc[m][n][i] = 0.f;

    prefetch(0, 0);
    CP_COMMIT();

    int stage = 0;
    for (int k0 = 0; k0 < DD; k0 += 32) {
        if (k0 + 32 < DD) {
            prefetch(k0 + 32, stage ^ 1);
            CP_COMMIT();
            CP_WAIT(1);
        } else {
            CP_WAIT(0);
        }
        __syncthreads();

        const uint32_t* As = dyn + stage * STG;
        const uint32_t* Ws = dyn + stage * STG + 128 * 36;
#pragma unroll
        for (int kk = 0; kk < 32; kk += 8) {
            uint32_t af[4][4], bf[4][2];
#pragma unroll
            for (int m = 0; m < 4; m++) {
                int mr = mOff + m * 16 + g;
                af[m][0] = As[mr * 36 + kk + t4];
                af[m][1] = As[(mr + 8) * 36 + kk + t4];
                af[m][2] = As[mr * 36 + kk + t4 + 4];
                af[m][3] = As[(mr + 8) * 36 + kk + t4 + 4];
            }
#pragma unroll
            for (int n = 0; n < 4; n++) {
                int nc = nOff + n * 8 + g;
                bf[n][0] = Ws[(kk + t4) * 136 + nc];
                bf[n][1] = Ws[(kk + t4 + 4) * 136 + nc];
            }
#pragma unroll
            for (int m = 0; m < 4; m++)
#pragma unroll
                for (int n = 0; n < 4; n++) mma_tf32(acc[m][n], af[m], bf[n]);
        }
        stage ^= 1;
        __syncthreads();
    }

#pragma unroll
    for (int m = 0; m < 4; m++) {
        int r0 = rowBase + mOff + m * 16 + g;
#pragma unroll
        for (int n = 0; n < 4; n++) {
            int c0 = colBase + nOff + n * 8 + t4 * 2;
            float2 bv = *(const float2*)(bias + c0);
            float v00 = acc[m][n][0] + bv.x, v01 = acc[m][n][1] + bv.y;
            float v10 = acc[m][n][2] + bv.x, v11 = acc[m][n][3] + bv.y;
            if (TF32OUT) {
                uint32_t* C = (uint32_t*)Cout;
                uint2 o0 = {f2tf(v00), f2tf(v01)};
                uint2 o1 = {f2tf(v10), f2tf(v11)};
                *(uint2*)(C + (size_t)r0 * DD + c0) = o0;
                *(uint2*)(C + (size_t)(r0 + 8) * DD + c0) = o1;
            } else {
                float* C = (float*)Cout;
                float2 o0 = {v00, v01};
                float2 o1 = {v10, v11};
                *(float2*)(C + (size_t)r0 * DD + c0) = o0;
                *(float2*)(C + (size_t)(r0 + 8) * DD + c0) = o1;
            }
        }
    }
}

__global__ __launch_bounds__(256, 2) void proj_qkv_tc(
    const uint32_t* __restrict__ qt, const uint32_t* __restrict__ kt,
    const uint32_t* __restrict__ vt,
    const uint32_t* __restrict__ wqt, const uint32_t* __restrict__ wkt,
    const uint32_t* __restrict__ wvt,
    const float* __restrict__ bq, const float* __restrict__ bk,
    const float* __restrict__ bv,
    uint32_t* __restrict__ qp, uint32_t* __restrict__ kp,
    uint32_t* __restrict__ vp)
{
    int z = blockIdx.z;
    const uint32_t* A = (z == 0) ? qt : (z == 1) ? kt : vt;
    const uint32_t* W = (z == 0) ? wqt : (z == 1) ? wkt : wvt;
    const float* B    = (z == 0) ? bq : (z == 1) ? bk : bv;
    uint32_t* C       = (z == 0) ? qp : (z == 1) ? kp : vp;
    gemm_async_core<true>(A, W, B, C);
}

__global__ __launch_bounds__(256, 2) void out_proj_tc(
    const uint32_t* __restrict__ A, const uint32_t* __restrict__ W,
    const float* __restrict__ B, float* __restrict__ C)
{
    gemm_async_core<false>(A, W, B, C);
}

// ---------------------------------------------------------------------------
// Logits: x = 0.125*<q,k> + mask*-1e9; writes e = exp(x) + per-(row,tile,warp)
// sumexp partials straight to gmem (sync-free epilogue). Dyn smem 69632 B.
// ---------------------------------------------------------------------------
__global__ __launch_bounds__(256, 2) void logits_tc(
    const uint32_t* __restrict__ qp, const uint32_t* __restrict__ kp,
    const float* __restrict__ mask, float* __restrict__ attn,
    float* __restrict__ part_l)
{
    extern __shared__ uint32_t dyn[];
    uint32_t* Qs = dyn;              // [128][68]
    uint32_t* Ks = dyn + 128 * 68;   // [128][68]

    const int tid = threadIdx.x;
    const int lane = tid & 31;
    const int warp = tid >> 5;
    const int g = lane >> 2, t4 = lane & 3;
    const int warpM = warp >> 2, warpN = warp & 3;
    const int bh = blockIdx.z, b = bh >> 4, h = bh & 15;
    const int s0 = blockIdx.y * 128, t0 = blockIdx.x * 128;

    const uint32_t* qb = qp + (size_t)b * SS * DD + (size_t)h * DH;
    const uint32_t* kb = kp + (size_t)b * SS * DD + (size_t)h * DH;

#pragma unroll
    for (int i = 0; i < 8; i++) {
        int l = tid + i * 256;
        int r = l >> 4, dc = (l & 15) * 4;
        CP_ASYNC16(smaddr(&Qs[r * 68 + dc]), qb + (size_t)(s0 + r) * DD + dc);
        CP_ASYNC16(smaddr(&Ks[r * 68 + dc]), kb + (size_t)(t0 + r) * DD + dc);
    }
    CP_COMMIT();
    CP_WAIT(0);
    __syncthreads();

    float acc[4][4][4];
#pragma unroll
    for (int m = 0; m < 4; m++)
#pragma unroll
        for (int n = 0; n < 4; n++)
#pragma unroll
            for (int i = 0; i < 4; i++) acc[m][n][i] = 0.f;

#pragma unroll
    for (int kk = 0; kk < 64; kk += 8) {
        uint32_t af[4][4], bf[4][2];
#pragma unroll
        for (int m = 0; m < 4; m++) {
            int mr = warpM * 64 + m * 16 + g;
            af[m][0] = Qs[mr * 68 + kk + t4];
            af[m][1] = Qs[(mr + 8) * 68 + kk + t4];
            af[m][2] = Qs[mr * 68 + kk + t4 + 4];
            af[m][3] = Qs[(mr + 8) * 68 + kk + t4 + 4];
        }
#pragma unroll
        for (int n = 0; n < 4; n++) {
            int nr = warpN * 32 + n * 8 + g;
            bf[n][0] = Ks[nr * 68 + kk + t4];
            bf[n][1] = Ks[nr * 68 + kk + t4 + 4];
        }
#pragma unroll
        for (int m = 0; m < 4; m++)
#pragma unroll
            for (int n = 0; n < 4; n++) mma_tf32(acc[m][n], af[m], bf[n]);
    }

    // e = exp(0.125*x + mask*-1e9)
#pragma unroll
    for (int n = 0; n < 4; n++) {
        int c0 = t0 + warpN * 32 + n * 8 + t4 * 2;
        float2 mv = *(const float2*)(mask + (size_t)b * SS + c0);
        float m0 = mv.x * -1e9f, m1 = mv.y * -1e9f;
#pragma unroll
        for (int m = 0; m < 4; m++) {
            acc[m][n][0] = __expf(acc[m][n][0] * 0.125f + m0);
            acc[m][n][1] = __expf(acc[m][n][1] * 0.125f + m1);
            acc[m][n][2] = __expf(acc[m][n][2] * 0.125f + m0);
            acc[m][n][3] = __expf(acc[m][n][3] * 0.125f + m1);
        }
    }

    // per-(row, 32-col warp slice) sumexp -> straight to gmem
#pragma unroll
    for (int m = 0; m < 4; m++)
#pragma unroll
        for (int hh = 0; hh < 2; hh++) {
            float s = 0.f;
#pragma unroll
            for (int n = 0; n < 4; n++)
                s += acc[m][n][hh * 2] + acc[m][n][hh * 2 + 1];
            s += __shfl_xor_sync(0xffffffffu, s, 1);
            s += __shfl_xor_sync(0xffffffffu, s, 2);
            if (t4 == 0) {
                int r = warpM * 64 + m * 16 + g + hh * 8;
                part_l[((size_t)bh * SS + s0 + r) * 64 + blockIdx.x * 4 + warpN] = s;
            }
        }

    // write e to gmem
    float* ob = attn + (size_t)bh * SS * SS;
#pragma unroll
    for (int m = 0; m < 4; m++) {
        int r0 = s0 + warpM * 64 + m * 16 + g;
#pragma unroll
        for (int n = 0; n < 4; n++) {
            int c0 = t0 + warpN * 32 + n * 8 + t4 * 2;
            float2 o0 = {acc[m][n][0], acc[m][n][1]};
            float2 o1 = {acc[m][n][2], acc[m][n][3]};
            *(float2*)(ob + (size_t)r0 * SS + c0) = o0;
            *(float2*)(ob + (size_t)(r0 + 8) * SS + c0) = o1;
        }
    }
}

// ---------------------------------------------------------------------------
// ctx + normalize fused, 64-row blocks, 3 CTAs/SM, double-buffered.
// Prologue reduces this block's 64 rows' invL from part_l (exclusive rows).
// p = e * invL; optional in-place p write (final attn); mma p @ v.
// Dynamic smem 37120 B: As[2][64][36], Vs[2][32][72], ILs[64].
// ---------------------------------------------------------------------------
template <bool WRITEP>
__global__ __launch_bounds__(256, 3) void ctx_tc(
    float* attn, const uint32_t* __restrict__ vp,
    const float* __restrict__ part_l, uint32_t* __restrict__ ctx)
{
    extern __shared__ uint32_t dynb[];
    uint32_t* Asm = dynb;                    // [2][64][36] = 4608
    uint32_t* Vsm = dynb + 2 * 64 * 36;      // [2][32][72] = 4608
    float* ILs = (float*)(dynb + 2 * 64 * 36 + 2 * 32 * 72);  // [64]

    const int tid = threadIdx.x;
    const int lane = tid & 31;
    const int warp = tid >> 5;
    const int g = lane >> 2, t4 = lane & 3;
    const int warpM = warp >> 1;   // 0..3 (16 rows each)
    const int warpN = warp & 1;    // 0..1 (32 cols each)
    const int bh = blockIdx.y, b = bh >> 4, h = bh & 15;
    const int s0 = blockIdx.x * 64;

    float* ab = attn + (size_t)bh * SS * SS;
    const uint32_t* vb = vp + (size_t)b * SS * DD + (size_t)h * DH;

    // ---- prologue: invL for our 64 rows (4 threads per row) ----
    {
        int r = tid >> 2, qd = tid & 3;
        const float* pr = part_l + ((size_t)bh * SS + s0 + r) * 64 + qd * 16;
        float s = 0.f;
#pragma unroll
        for (int i = 0; i < 16; i++) s += pr[i];
        s += __shfl_xor_sync(0xffffffffu, s, 1);
        s += __shfl_xor_sync(0xffffffffu, s, 2);
        if (qd == 0) ILs[r] = 1.0f / s;
    }
    __syncthreads();

    const int arow = tid >> 3;           // 0..31 (+32*i)
    const int acol = (tid & 7) * 4;      // 0..28
    const int vrow = tid >> 4;           // 0..15 (+16*i)
    const int vcol = (tid & 15) * 4;     // 0..60

    float ILr[2] = {ILs[arow], ILs[arow + 32]};

    float4 a4[2];
    uint4 v4[2];

    auto fetch = [&](int kt) {
#pragma unroll
        for (int i = 0; i < 2; i++) {
            int r = arow + 32 * i;
            a4[i] = *(const float4*)(ab + (size_t)(s0 + r) * SS + kt * 32 + acol);
        }
#pragma unroll
        for (int i = 0; i < 2; i++)
            v4[i] = *(const uint4*)(vb + (size_t)(kt * 32 + vrow + 16 * i) * DD + vcol);
    };
    auto commit = [&](int kt, int st) {
#pragma unroll
        for (int i = 0; i < 2; i++) {
            int r = arow + 32 * i;
            float4 p;
            p.x = a4[i].x * ILr[i]; p.y = a4[i].y * ILr[i];
            p.z = a4[i].z * ILr[i]; p.w = a4[i].w * ILr[i];
            if (WRITEP)
                *(float4*)(ab + (size_t)(s0 + r) * SS + kt * 32 + acol) = p;
            uint4 u = {f2tf(p.x), f2tf(p.y), f2tf(p.z), f2tf(p.w)};
            *(uint4*)&Asm[st * (64 * 36) + r * 36 + acol] = u;
        }
#pragma unroll
        for (int i = 0; i < 2; i++)
            *(uint4*)&Vsm[st * (32 * 72) + (vrow + 16 * i) * 72 + vcol] = v4[i];
    };

    float acc[4][4];
#pragma unroll
    for (int n = 0; n < 4; n++)
#pragma unroll
        for (int i = 0; i < 4; i++) acc[n][i] = 0.f;

    fetch(0);
    commit(0, 0);
    __syncthreads();

    for (int kt = 0; kt < 64; kt++) {
        const int cur = kt & 1;
        if (kt + 1 < 64) fetch(kt + 1);

        const uint32_t* Ac = Asm + cur * (64 * 36);
        const uint32_t* Vc = Vsm + cur * (32 * 72);
#pragma unroll
        for (int kk = 0; kk < 32; kk += 8) {
            uint32_t af[4], bf[4][2];
            int mr = warpM * 16 + g;
            af[0] = Ac[mr * 36 + kk + t4];
            af[1] = Ac[(mr + 8) * 36 + kk + t4];
            af[2] = Ac[mr * 36 + kk + t4 + 4];
            af[3] = Ac[(mr + 8) * 36 + kk + t4 + 4];
#pragma unroll
            for (int n = 0; n < 4; n++) {
                int nc = warpN * 32 + n * 8 + g;
                bf[n][0] = Vc[(kk + t4) * 72 + nc];
                bf[n][1] = Vc[(kk + t4 + 4) * 72 + nc];
            }
#pragma unroll
            for (int n = 0; n < 4; n++) mma_tf32(acc[n], af, bf[n]);
        }
        if (kt + 1 < 64) commit(kt + 1, cur ^ 1);
        __syncthreads();
    }

    {
        int r0 = s0 + warpM * 16 + g;
#pragma unroll
        for (int n = 0; n < 4; n++) {
            int c0 = warpN * 32 + n * 8 + t4 * 2;
            uint2 o0 = {f2tf(acc[n][0]), f2tf(acc[n][1])};
            uint2 o1 = {f2tf(acc[n][2]), f2tf(acc[n][3])};
            *(uint2*)(ctx + ((size_t)b * SS + r0) * DD + h * DH + c0) = o0;
            *(uint2*)(ctx + ((size_t)b * SS + r0 + 8) * DD + h * DH + c0) = o1;
        }
    }
}

// ---------------------------------------------------------------------------
extern "C" void kernel_launch(void* const* d_in, const int* in_sizes, int n_in,
                              void* d_out, int out_size)
{
    const float* q    = (const float*)d_in[0];
    const float* k    = (const float*)d_in[1];
    const float* v    = (const float*)d_in[2];
    const float* mask = (const float*)d_in[3];
    const float* wq   = (const float*)d_in[4];
    const float* bq   = (const float*)d_in[5];
    const float* wk   = (const float*)d_in[6];
    const float* bk   = (const float*)d_in[7];
    const float* wv   = (const float*)d_in[8];
    const float* bv   = (const float*)d_in[9];
    const float* wo   = (const float*)d_in[10];
    const float* bo   = (const float*)d_in[11];
    float* out = (float*)d_out;

    uint32_t *qt, *kt, *vt, *wqt, *wkt, *wvt, *wot, *qp, *kp, *vp, *ctx;
    float *attn, *pl;
    cudaGetSymbolAddress((void**)&qt,  g_qt);
    cudaGetSymbolAddress((void**)&kt,  g_kt);
    cudaGetSymbolAddress((void**)&vt,  g_vt);
    cudaGetSymbolAddress((void**)&wqt, g_wqt);
    cudaGetSymbolAddress((void**)&wkt, g_wkt);
    cudaGetSymbolAddress((void**)&wvt, g_wvt);
    cudaGetSymbolAddress((void**)&wot, g_wot);
    cudaGetSymbolAddress((void**)&qp,  g_qp);
    cudaGetSymbolAddress((void**)&kp,  g_kp);
    cudaGetSymbolAddress((void**)&vp,  g_vp);
    cudaGetSymbolAddress((void**)&ctx, g_ctx);
    cudaGetSymbolAddress((void**)&pl,  g_part_l);

    bool attn_in_out = ((size_t)out_size >= OUT_ELEMS + ATTN_ELEMS);
    if (attn_in_out) {
        attn = out + OUT_ELEMS;
    } else {
        cudaGetSymbolAddress((void**)&attn, g_attn_fb);
    }

    const int DYN_G   = 2 * (128 * 36 + 32 * 136) * 4;             // 71680
    const int DYN_L   = (128 * 68 * 2) * 4;                        // 69632
    const int DYN_CTX = (2 * 64 * 36 + 2 * 32 * 72) * 4 + 64 * 4;  // 37120
    cudaFuncSetAttribute(proj_qkv_tc, cudaFuncAttributeMaxDynamicSharedMemorySize, DYN_G);
    cudaFuncSetAttribute(out_proj_tc, cudaFuncAttributeMaxDynamicSharedMemorySize, DYN_G);
    cudaFuncSetAttribute(logits_tc,   cudaFuncAttributeMaxDynamicSharedMemorySize, DYN_L);
    cudaFuncSetAttribute(ctx_tc<true>,  cudaFuncAttributeMaxDynamicSharedMemorySize, DYN_CTX);
    cudaFuncSetAttribute(ctx_tc<false>, cudaFuncAttributeMaxDynamicSharedMemorySize, DYN_CTX);

    conv_all<<<2048, 256>>>(
        (const float4*)q, (const float4*)k, (const float4*)v,
        (const float4*)wq, (const float4*)wk, (const float4*)wv,
        (const float4*)wo,
        (uint4*)qt, (uint4*)kt, (uint4*)vt,
        (uint4*)wqt, (uint4*)wkt, (uint4*)wvt, (uint4*)wot);

    proj_qkv_tc<<<dim3(DD / 128, MROWS / 128, 3), 256, DYN_G>>>(
        qt, kt, vt, wqt, wkt, wvt, bq, bk, bv, qp, kp, vp);

    logits_tc<<<dim3(SS / 128, SS / 128, BB * HH), 256, DYN_L>>>(
        qp, kp, mask, attn, pl);

    if (attn_in_out)
        ctx_tc<true><<<dim3(SS / 64, BB * HH), 256, DYN_CTX>>>(attn, vp, pl, ctx);
    else
        ctx_tc<false><<<dim3(SS / 64, BB * HH), 256, DYN_CTX>>>(attn, vp, pl, ctx);

    out_proj_tc<<<dim3(DD / 128, MROWS / 128), 256, DYN_G>>>(ctx, wot, bo, out);
}

// round 8
// speedup vs baseline: 1.1002x; 1.1002x over previous
#include <cuda_runtime.h>
#include <stdint.h>
#include <math.h>

#define BB 2
#define HH 16
#define SS 2048
#define DD 1024
#define DH 64
#define MROWS (BB*SS)          // 4096
#define NROWS_TOT (BB*HH*SS)   // 65536 attn rows

static const size_t OUT_ELEMS  = (size_t)BB * SS * DD;        // 4,194,304
static const size_t ATTN_ELEMS = (size_t)BB * HH * SS * SS;   // 134,217,728

// Scratch (__device__ globals; allocation in kernel_launch is forbidden)
__device__ uint32_t g_qt[MROWS * DD];
__device__ uint32_t g_kt[MROWS * DD];
__device__ uint32_t g_vt[MROWS * DD];
__device__ uint32_t g_wqt[DD * DD];
__device__ uint32_t g_wkt[DD * DD];
__device__ uint32_t g_wvt[DD * DD];
__device__ uint32_t g_wot[DD * DD];
__device__ uint32_t g_qp[MROWS * DD];
__device__ uint32_t g_kp[MROWS * DD];
__device__ uint32_t g_vp[MROWS * DD];
__device__ uint32_t g_ctx[MROWS * DD];
__device__ float g_attn_fb[(size_t)BB * HH * SS * SS];
__device__ float g_part_l[(size_t)NROWS_TOT * 64];   // 64 partials per row
__device__ float g_row_il[NROWS_TOT];

// ---------------------------------------------------------------------------
__device__ __forceinline__ uint32_t f2tf(float f) {
    uint32_t u;
    asm("cvt.rna.tf32.f32 %0, %1;" : "=r"(u) : "f"(f));
    return u;
}

__device__ __forceinline__ void mma_tf32(float c[4], const uint32_t a[4],
                                         const uint32_t b[2]) {
    asm volatile(
        "mma.sync.aligned.m16n8k8.row.col.f32.tf32.tf32.f32 "
        "{%0,%1,%2,%3}, {%4,%5,%6,%7}, {%8,%9}, {%0,%1,%2,%3};\n"
        : "+f"(c[0]), "+f"(c[1]), "+f"(c[2]), "+f"(c[3])
        : "r"(a[0]), "r"(a[1]), "r"(a[2]), "r"(a[3]), "r"(b[0]), "r"(b[1]));
}

__device__ __forceinline__ uint32_t smaddr(const void* p) {
    return (uint32_t)__cvta_generic_to_shared(p);
}
#define CP_ASYNC16(dst, src) \
    asm volatile("cp.async.cg.shared.global [%0], [%1], 16;" :: "r"(dst), "l"(src))
#define CP_COMMIT() asm volatile("cp.async.commit_group;")
#define CP_WAIT(n)  asm volatile("cp.async.wait_group %0;" :: "n"(n))

// ---------------------------------------------------------------------------
// One fused f32 -> tf32 conversion over all 7 tensors (grid-stride).
// ---------------------------------------------------------------------------
__global__ __launch_bounds__(256) void conv_all(
    const float4* __restrict__ q, const float4* __restrict__ k,
    const float4* __restrict__ v,
    const float4* __restrict__ wq, const float4* __restrict__ wk,
    const float4* __restrict__ wv, const float4* __restrict__ wo,
    uint4* __restrict__ qt, uint4* __restrict__ kt, uint4* __restrict__ vt,
    uint4* __restrict__ wqt, uint4* __restrict__ wkt, uint4* __restrict__ wvt,
    uint4* __restrict__ wot)
{
    const int NQ = MROWS * DD / 4;   // 1048576 (pow2)
    const int NW = DD * DD / 4;      // 262144  (pow2)
    const int TOT = 3 * NQ + 4 * NW;
    for (int i = blockIdx.x * 256 + threadIdx.x; i < TOT; i += gridDim.x * 256) {
        const float4* src; uint4* dst; int off;
        if (i < 3 * NQ) {
            int s = i >> 20;
            off = i & (NQ - 1);
            src = (s == 0) ? q : (s == 1) ? k : v;
            dst = (s == 0) ? qt : (s == 1) ? kt : vt;
        } else {
            int j = i - 3 * NQ;
            int s = j >> 18;
            off = j & (NW - 1);
            src = (s == 0) ? wq : (s == 1) ? wk : (s == 2) ? wv : wo;
            dst = (s == 0) ? wqt : (s == 1) ? wkt : (s == 2) ? wvt : wot;
        }
        float4 x = src[off];
        uint4 u = {f2tf(x.x), f2tf(x.y), f2tf(x.z), f2tf(x.w)};
        dst[off] = u;
    }
}

// ---------------------------------------------------------------------------
// Async GEMM core: C[4096,1024] = A @ W + bias (tf32-bit operands).
// Block 128x128, BK=32, 2-stage cp.async. Dynamic smem 71680 B.
// ---------------------------------------------------------------------------
template <bool TF32OUT>
__device__ __forceinline__ void gemm_async_core(
    const uint32_t* __restrict__ A, const uint32_t* __restrict__ W,
    const float* __restrict__ bias, void* __restrict__ Cout)
{
    extern __shared__ uint32_t dyn[];
    const int STG = 128 * 36 + 32 * 136;

    const int tid = threadIdx.x;
    const int lane = tid & 31;
    const int warp = tid >> 5;
    const int g = lane >> 2, t4 = lane & 3;
    const int warpM = warp >> 2, warpN = warp & 3;
    const int rowBase = blockIdx.y * 128;
    const int colBase = blockIdx.x * 128;
    const int mOff = warpM * 64, nOff = warpN * 32;

    const int ar = tid >> 3, ak = (tid & 7) * 4;
    auto prefetch = [&](int k0, int s) {
        uint32_t* As = dyn + s * STG;
        uint32_t* Ws = dyn + s * STG + 128 * 36;
#pragma unroll
        for (int i = 0; i < 4; i++) {
            int r = ar + i * 32;
            CP_ASYNC16(smaddr(&As[r * 36 + ak]),
                       A + (size_t)(rowBase + r) * DD + k0 + ak);
        }
#pragma unroll
        for (int i = 0; i < 4; i++) {
            int l = tid + i * 256;
            int r = l >> 5, nc = (l & 31) * 4;
            CP_ASYNC16(smaddr(&Ws[r * 136 + nc]),
                       W + (size_t)(k0 + r) * DD + colBase + nc);
        }
    };

    float acc[4][4][4];
#pragma unroll
    for (int m = 0; m < 4; m++)
#pragma unroll
        for (int n = 0; n < 4; n++)
#pragma unroll
            for (int i = 0; i < 4; i++) acc[m][n][i] = 0.f;

    prefetch(0, 0);
    CP_COMMIT();

    int stage = 0;
    for (int k0 = 0; k0 < DD; k0 += 32) {
        if (k0 + 32 < DD) {
            prefetch(k0 + 32, stage ^ 1);
            CP_COMMIT();
            CP_WAIT(1);
        } else {
            CP_WAIT(0);
        }
        __syncthreads();

        const uint32_t* As = dyn + stage * STG;
        const uint32_t* Ws = dyn + stage * STG + 128 * 36;
#pragma unroll
        for (int kk = 0; kk < 32; kk += 8) {
            uint32_t af[4][4], bf[4][2];
#pragma unroll
            for (int m = 0; m < 4; m++) {
                int mr = mOff + m * 16 + g;
                af[m][0] = As[mr * 36 + kk + t4];
                af[m][1] = As[(mr + 8) * 36 + kk + t4];
                af[m][2] = As[mr * 36 + kk + t4 + 4];
                af[m][3] = As[(mr + 8) * 36 + kk + t4 + 4];
            }
#pragma unroll
            for (int n = 0; n < 4; n++) {
                int nc = nOff + n * 8 + g;
                bf[n][0] = Ws[(kk + t4) * 136 + nc];
                bf[n][1] = Ws[(kk + t4 + 4) * 136 + nc];
            }
#pragma unroll
            for (int m = 0; m < 4; m++)
#pragma unroll
                for (int n = 0; n < 4; n++) mma_tf32(acc[m][n], af[m], bf[n]);
        }
        stage ^= 1;
        __syncthreads();
    }

#pragma unroll
    for (int m = 0; m < 4; m++) {
        int r0 = rowBase + mOff + m * 16 + g;
#pragma unroll
        for (int n = 0; n < 4; n++) {
            int c0 = colBase + nOff + n * 8 + t4 * 2;
            float2 bv = *(const float2*)(bias + c0);
            float v00 = acc[m][n][0] + bv.x, v01 = acc[m][n][1] + bv.y;
            float v10 = acc[m][n][2] + bv.x, v11 = acc[m][n][3] + bv.y;
            if (TF32OUT) {
                uint32_t* C = (uint32_t*)Cout;
                uint2 o0 = {f2tf(v00), f2tf(v01)};
                uint2 o1 = {f2tf(v10), f2tf(v11)};
                *(uint2*)(C + (size_t)r0 * DD + c0) = o0;
                *(uint2*)(C + (size_t)(r0 + 8) * DD + c0) = o1;
            } else {
                float* C = (float*)Cout;
                float2 o0 = {v00, v01};
                float2 o1 = {v10, v11};
                *(float2*)(C + (size_t)r0 * DD + c0) = o0;
                *(float2*)(C + (size_t)(r0 + 8) * DD + c0) = o1;
            }
        }
    }
}

__global__ __launch_bounds__(256, 2) void proj_qkv_tc(
    const uint32_t* __restrict__ qt, const uint32_t* __restrict__ kt,
    const uint32_t* __restrict__ vt,
    const uint32_t* __restrict__ wqt, const uint32_t* __restrict__ wkt,
    const uint32_t* __restrict__ wvt,
    const float* __restrict__ bq, const float* __restrict__ bk,
    const float* __restrict__ bv,
    uint32_t* __restrict__ qp, uint32_t* __restrict__ kp,
    uint32_t* __restrict__ vp)
{
    int z = blockIdx.z;
    const uint32_t* A = (z == 0) ? qt : (z == 1) ? kt : vt;
    const uint32_t* W = (z == 0) ? wqt : (z == 1) ? wkt : wvt;
    const float* B    = (z == 0) ? bq : (z == 1) ? bk : bv;
    uint32_t* C       = (z == 0) ? qp : (z == 1) ? kp : vp;
    gemm_async_core<true>(A, W, B, C);
}

__global__ __launch_bounds__(256, 2) void out_proj_tc(
    const uint32_t* __restrict__ A, const uint32_t* __restrict__ W,
    const float* __restrict__ B, float* __restrict__ C)
{
    gemm_async_core<false>(A, W, B, C);
}

// ---------------------------------------------------------------------------
// Logits: x = 0.125*<q,k> + mask*-1e9; writes e = tf32_round(exp(x)) so the
// ctx kernel can cp.async the bits directly as MMA operands. Sync-free
// epilogue: per-(row, 32-col slice) sumexp of ROUNDED e -> gmem partials.
// ---------------------------------------------------------------------------
__global__ __launch_bounds__(256, 2) void logits_tc(
    const uint32_t* __restrict__ qp, const uint32_t* __restrict__ kp,
    const float* __restrict__ mask, float* __restrict__ attn,
    float* __restrict__ part_l)
{
    extern __shared__ uint32_t dyn[];
    uint32_t* Qs = dyn;              // [128][68]
    uint32_t* Ks = dyn + 128 * 68;   // [128][68]

    const int tid = threadIdx.x;
    const int lane = tid & 31;
    const int warp = tid >> 5;
    const int g = lane >> 2, t4 = lane & 3;
    const int warpM = warp >> 2, warpN = warp & 3;
    const int bh = blockIdx.z, b = bh >> 4, h = bh & 15;
    const int s0 = blockIdx.y * 128, t0 = blockIdx.x * 128;

    const uint32_t* qb = qp + (size_t)b * SS * DD + (size_t)h * DH;
    const uint32_t* kb = kp + (size_t)b * SS * DD + (size_t)h * DH;

#pragma unroll
    for (int i = 0; i < 8; i++) {
        int l = tid + i * 256;
        int r = l >> 4, dc = (l & 15) * 4;
        CP_ASYNC16(smaddr(&Qs[r * 68 + dc]), qb + (size_t)(s0 + r) * DD + dc);
        CP_ASYNC16(smaddr(&Ks[r * 68 + dc]), kb + (size_t)(t0 + r) * DD + dc);
    }
    CP_COMMIT();
    CP_WAIT(0);
    __syncthreads();

    float acc[4][4][4];
#pragma unroll
    for (int m = 0; m < 4; m++)
#pragma unroll
        for (int n = 0; n < 4; n++)
#pragma unroll
            for (int i = 0; i < 4; i++) acc[m][n][i] = 0.f;

#pragma unroll
    for (int kk = 0; kk < 64; kk += 8) {
        uint32_t af[4][4], bf[4][2];
#pragma unroll
        for (int m = 0; m < 4; m++) {
            int mr = warpM * 64 + m * 16 + g;
            af[m][0] = Qs[mr * 68 + kk + t4];
            af[m][1] = Qs[(mr + 8) * 68 + kk + t4];
            af[m][2] = Qs[mr * 68 + kk + t4 + 4];
            af[m][3] = Qs[(mr + 8) * 68 + kk + t4 + 4];
        }
#pragma unroll
        for (int n = 0; n < 4; n++) {
            int nr = warpN * 32 + n * 8 + g;
            bf[n][0] = Ks[nr * 68 + kk + t4];
            bf[n][1] = Ks[nr * 68 + kk + t4 + 4];
        }
#pragma unroll
        for (int m = 0; m < 4; m++)
#pragma unroll
            for (int n = 0; n < 4; n++) mma_tf32(acc[m][n], af[m], bf[n]);
    }

    // e = tf32_round(exp(0.125*x + mask*-1e9))
#pragma unroll
    for (int n = 0; n < 4; n++) {
        int c0 = t0 + warpN * 32 + n * 8 + t4 * 2;
        float2 mv = *(const float2*)(mask + (size_t)b * SS + c0);
        float m0 = mv.x * -1e9f, m1 = mv.y * -1e9f;
#pragma unroll
        for (int m = 0; m < 4; m++) {
            acc[m][n][0] = __uint_as_float(f2tf(__expf(acc[m][n][0] * 0.125f + m0)));
            acc[m][n][1] = __uint_as_float(f2tf(__expf(acc[m][n][1] * 0.125f + m1)));
            acc[m][n][2] = __uint_as_float(f2tf(__expf(acc[m][n][2] * 0.125f + m0)));
            acc[m][n][3] = __uint_as_float(f2tf(__expf(acc[m][n][3] * 0.125f + m1)));
        }
    }

    // per-(row, 32-col warp slice) sumexp (of rounded e) -> straight to gmem
#pragma unroll
    for (int m = 0; m < 4; m++)
#pragma unroll
        for (int hh = 0; hh < 2; hh++) {
            float s = 0.f;
#pragma unroll
            for (int n = 0; n < 4; n++)
                s += acc[m][n][hh * 2] + acc[m][n][hh * 2 + 1];
            s += __shfl_xor_sync(0xffffffffu, s, 1);
            s += __shfl_xor_sync(0xffffffffu, s, 2);
            if (t4 == 0) {
                int r = warpM * 64 + m * 16 + g + hh * 8;
                part_l[((size_t)bh * SS + s0 + r) * 64 + blockIdx.x * 4 + warpN] = s;
            }
        }

    // write e to gmem
    float* ob = attn + (size_t)bh * SS * SS;
#pragma unroll
    for (int m = 0; m < 4; m++) {
        int r0 = s0 + warpM * 64 + m * 16 + g;
#pragma unroll
        for (int n = 0; n < 4; n++) {
            int c0 = t0 + warpN * 32 + n * 8 + t4 * 2;
            float2 o0 = {acc[m][n][0], acc[m][n][1]};
            float2 o1 = {acc[m][n][2], acc[m][n][3]};
            *(float2*)(ob + (size_t)r0 * SS + c0) = o0;
            *(float2*)(ob + (size_t)(r0 + 8) * SS + c0) = o1;
        }
    }
}

// ---------------------------------------------------------------------------
// Per-row: invL = 1 / sum of 64 partials.
// ---------------------------------------------------------------------------
__global__ __launch_bounds__(256) void row_invl(
    const float4* __restrict__ pl, float* __restrict__ ril)
{
    int row = blockIdx.x * 256 + threadIdx.x;
    const float4* p = pl + (size_t)row * 16;
    float L = 0.f;
#pragma unroll
    for (int i = 0; i < 16; i++) {
        float4 v = p[i];
        L += (v.x + v.y) + (v.z + v.w);
    }
    ril[row] = 1.0f / L;
}

// ---------------------------------------------------------------------------
// ctx: 128-row blocks, 3-stage cp.async pipeline, ONE sync per iter.
// e bits in gmem are already tf32 -> cp.async straight to smem, MMA directly.
// invL commutes with the GEMM: acc is scaled once in the epilogue.
// p-write (if needed) re-reads the smem tile: p = e * invL, coalesced STG.
// Dynamic smem 82944 B: 3 x (As[128][36] + Vs[32][72]).
// ---------------------------------------------------------------------------
template <bool WRITEP>
__global__ __launch_bounds__(256, 2) void ctx_tc(
    float* attn, const uint32_t* __restrict__ vp,
    const float* __restrict__ rowIL, uint32_t* __restrict__ ctx)
{
    extern __shared__ uint32_t dynb[];
    const int ASZ = 128 * 36, VSZ = 32 * 72, STG3 = ASZ + VSZ;

    const int tid = threadIdx.x;
    const int lane = tid & 31;
    const int warp = tid >> 5;
    const int g = lane >> 2, t4 = lane & 3;
    const int warpM = warp >> 1, warpN = warp & 1;
    const int bh = blockIdx.y, b = bh >> 4, h = bh & 15;
    const int s0 = blockIdx.x * 128;

    const uint32_t* ae = (const uint32_t*)attn + (size_t)bh * SS * SS;
    const uint32_t* vb = vp + (size_t)b * SS * DD + (size_t)h * DH;

    const int ar = tid >> 3, ac = (tid & 7) * 4;    // A loader: rows +32*i
    const int vr = tid >> 4, vc = (tid & 15) * 4;   // V loader: rows +16*i

    float ILr[4];
#pragma unroll
    for (int i = 0; i < 4; i++)
        ILr[i] = __ldg(rowIL + (size_t)bh * SS + s0 + ar + 32 * i);

    auto prefetch = [&](int kt, int st) {
        uint32_t* As = dynb + st * STG3;
        uint32_t* Vs = dynb + st * STG3 + ASZ;
#pragma unroll
        for (int i = 0; i < 4; i++) {
            int r = ar + 32 * i;
            CP_ASYNC16(smaddr(&As[r * 36 + ac]),
                       ae + (size_t)(s0 + r) * SS + kt * 32 + ac);
        }
#pragma unroll
        for (int i = 0; i < 2; i++) {
            int r = vr + 16 * i;
            CP_ASYNC16(smaddr(&Vs[r * 72 + vc]),
                       vb + (size_t)(kt * 32 + r) * DD + vc);
        }
    };

    float acc[2][4][4];
#pragma unroll
    for (int m = 0; m < 2; m++)
#pragma unroll
        for (int n = 0; n < 4; n++)
#pragma unroll
            for (int i = 0; i < 4; i++) acc[m][n][i] = 0.f;

    prefetch(0, 0); CP_COMMIT();
    prefetch(1, 1); CP_COMMIT();

    for (int kt = 0; kt < 64; kt++) {
        const int cur = kt % 3;
        if (kt < 63) { CP_WAIT(1); } else { CP_WAIT(0); }
        __syncthreads();
        if (kt + 2 < 64) { prefetch(kt + 2, (kt + 2) % 3); CP_COMMIT(); }

        const uint32_t* Ac = dynb + cur * STG3;
        const uint32_t* Vc = Ac + ASZ;
#pragma unroll
        for (int kk = 0; kk < 32; kk += 8) {
            uint32_t af[2][4], bf[4][2];
#pragma unroll
            for (int m = 0; m < 2; m++) {
                int mr = warpM * 32 + m * 16 + g;
                af[m][0] = Ac[mr * 36 + kk + t4];
                af[m][1] = Ac[(mr + 8) * 36 + kk + t4];
                af[m][2] = Ac[mr * 36 + kk + t4 + 4];
                af[m][3] = Ac[(mr + 8) * 36 + kk + t4 + 4];
            }
#pragma unroll
            for (int n = 0; n < 4; n++) {
                int nc = warpN * 32 + n * 8 + g;
                bf[n][0] = Vc[(kk + t4) * 72 + nc];
                bf[n][1] = Vc[(kk + t4 + 4) * 72 + nc];
            }
#pragma unroll
            for (int m = 0; m < 2; m++)
#pragma unroll
                for (int n = 0; n < 4; n++) mma_tf32(acc[m][n], af[m], bf[n]);
        }

        if (WRITEP) {
#pragma unroll
            for (int i = 0; i < 4; i++) {
                int r = ar + 32 * i;
                float4 e4 = *(const float4*)&Ac[r * 36 + ac];
                float4 p = {e4.x * ILr[i], e4.y * ILr[i],
                            e4.z * ILr[i], e4.w * ILr[i]};
                *(float4*)(attn + (size_t)bh * SS * SS +
                           (size_t)(s0 + r) * SS + kt * 32 + ac) = p;
            }
        }
    }

#pragma unroll
    for (int m = 0; m < 2; m++) {
        int r0 = warpM * 32 + m * 16 + g;
        float il0 = __ldg(rowIL + (size_t)bh * SS + s0 + r0);
        float il1 = __ldg(rowIL + (size_t)bh * SS + s0 + r0 + 8);
#pragma unroll
        for (int n = 0; n < 4; n++) {
            int c0 = warpN * 32 + n * 8 + t4 * 2;
            uint2 o0 = {f2tf(acc[m][n][0] * il0), f2tf(acc[m][n][1] * il0)};
            uint2 o1 = {f2tf(acc[m][n][2] * il1), f2tf(acc[m][n][3] * il1)};
            *(uint2*)(ctx + ((size_t)b * SS + s0 + r0) * DD + h * DH + c0) = o0;
            *(uint2*)(ctx + ((size_t)b * SS + s0 + r0 + 8) * DD + h * DH + c0) = o1;
        }
    }
}

// ---------------------------------------------------------------------------
extern "C" void kernel_launch(void* const* d_in, const int* in_sizes, int n_in,
                              void* d_out, int out_size)
{
    const float* q    = (const float*)d_in[0];
    const float* k    = (const float*)d_in[1];
    const float* v    = (const float*)d_in[2];
    const float* mask = (const float*)d_in[3];
    const float* wq   = (const float*)d_in[4];
    const float* bq   = (const float*)d_in[5];
    const float* wk   = (const float*)d_in[6];
    const float* bk   = (const float*)d_in[7];
    const float* wv   = (const float*)d_in[8];
    const float* bv   = (const float*)d_in[9];
    const float* wo   = (const float*)d_in[10];
    const float* bo   = (const float*)d_in[11];
    float* out = (float*)d_out;

    uint32_t *qt, *kt, *vt, *wqt, *wkt, *wvt, *wot, *qp, *kp, *vp, *ctx;
    float *attn, *pl, *ril;
    cudaGetSymbolAddress((void**)&qt,  g_qt);
    cudaGetSymbolAddress((void**)&kt,  g_kt);
    cudaGetSymbolAddress((void**)&vt,  g_vt);
    cudaGetSymbolAddress((void**)&wqt, g_wqt);
    cudaGetSymbolAddress((void**)&wkt, g_wkt);
    cudaGetSymbolAddress((void**)&wvt, g_wvt);
    cudaGetSymbolAddress((void**)&wot, g_wot);
    cudaGetSymbolAddress((void**)&qp,  g_qp);
    cudaGetSymbolAddress((void**)&kp,  g_kp);
    cudaGetSymbolAddress((void**)&vp,  g_vp);
    cudaGetSymbolAddress((void**)&ctx, g_ctx);
    cudaGetSymbolAddress((void**)&pl,  g_part_l);
    cudaGetSymbolAddress((void**)&ril, g_row_il);

    bool attn_in_out = ((size_t)out_size >= OUT_ELEMS + ATTN_ELEMS);
    if (attn_in_out) {
        attn = out + OUT_ELEMS;
    } else {
        cudaGetSymbolAddress((void**)&attn, g_attn_fb);
    }

    const int DYN_G   = 2 * (128 * 36 + 32 * 136) * 4;   // 71680
    const int DYN_L   = (128 * 68 * 2) * 4;              // 69632
    const int DYN_CTX = 3 * (128 * 36 + 32 * 72) * 4;    // 82944
    cudaFuncSetAttribute(proj_qkv_tc, cudaFuncAttributeMaxDynamicSharedMemorySize, DYN_G);
    cudaFuncSetAttribute(out_proj_tc, cudaFuncAttributeMaxDynamicSharedMemorySize, DYN_G);
    cudaFuncSetAttribute(logits_tc,   cudaFuncAttributeMaxDynamicSharedMemorySize, DYN_L);
    cudaFuncSetAttribute(ctx_tc<true>,  cudaFuncAttributeMaxDynamicSharedMemorySize, DYN_CTX);
    cudaFuncSetAttribute(ctx_tc<false>, cudaFuncAttributeMaxDynamicSharedMemorySize, DYN_CTX);

    conv_all<<<2048, 256>>>(
        (const float4*)q, (const float4*)k, (const float4*)v,
        (const float4*)wq, (const float4*)wk, (const float4*)wv,
        (const float4*)wo,
        (uint4*)qt, (uint4*)kt, (uint4*)vt,
        (uint4*)wqt, (uint4*)wkt, (uint4*)wvt, (uint4*)wot);

    proj_qkv_tc<<<dim3(DD / 128, MROWS / 128, 3), 256, DYN_G>>>(
        qt, kt, vt, wqt, wkt, wvt, bq, bk, bv, qp, kp, vp);

    logits_tc<<<dim3(SS / 128, SS / 128, BB * HH), 256, DYN_L>>>(
        qp, kp, mask, attn, pl);

    row_invl<<<NROWS_TOT / 256, 256>>>((const float4*)pl, ril);

    if (attn_in_out)
        ctx_tc<true><<<dim3(SS / 128, BB * HH), 256, DYN_CTX>>>(attn, vp, ril, ctx);
    else
        ctx_tc<false><<<dim3(SS / 128, BB * HH), 256, DYN_CTX>>>(attn, vp, ril, ctx);

    out_proj_tc<<<dim3(DD / 128, MROWS / 128), 256, DYN_G>>>(ctx, wot, bo, out);
}

// round 9
// speedup vs baseline: 1.5475x; 1.4065x over previous
#include <cuda_runtime.h>
#include <cuda_fp16.h>
#include <stdint.h>
#include <math.h>

#define BB 2
#define HH 16
#define SS 2048
#define DD 1024
#define DH 64
#define MROWS (BB*SS)          // 4096
#define NROWS_TOT (BB*HH*SS)   // 65536
#define KU 512                 // u32 (fp16x2) per DD row
#define TU 1024                // u32 (fp16x2) per SS row

static const size_t OUT_ELEMS  = (size_t)BB * SS * DD;        // 4,194,304
static const size_t ATTN_ELEMS = (size_t)BB * HH * SS * SS;   // 134,217,728

// Scratch (__device__ globals)
__device__ uint32_t g_qh[MROWS * KU];          // fp16(q)
__device__ uint32_t g_kh[MROWS * KU];
__device__ uint32_t g_vh[MROWS * KU];
__device__ uint32_t g_wqp[(DD/2) * DD];        // W packed along k: u32 = (W[2k'][n], W[2k'+1][n])
__device__ uint32_t g_wkp[(DD/2) * DD];
__device__ uint32_t g_wvp[(DD/2) * DD];
__device__ uint32_t g_wop[(DD/2) * DD];
__device__ uint32_t g_qp[MROWS * KU];          // projected, fp16 [t][d]
__device__ uint32_t g_kp[MROWS * KU];
__device__ uint32_t g_vp[MROWS * KU];
__device__ uint32_t g_vpt[(size_t)BB*HH*DH*TU];// V head-transposed [bh][d][t] fp16
__device__ uint32_t g_ctx[MROWS * KU];         // ctx fp16
__device__ uint32_t g_e[(size_t)BB*HH*SS*(SS/2)];  // e fp16 [bh][s][t]
__device__ float g_part_l[(size_t)NROWS_TOT * 64];
__device__ float g_row_il[NROWS_TOT];

// ---------------------------------------------------------------------------
__device__ __forceinline__ uint32_t packh2(float a, float b) {
    __half2 h = __floats2half2_rn(a, b);
    return *reinterpret_cast<uint32_t*>(&h);
}
__device__ __forceinline__ float2 unpackh2(uint32_t u) {
    __half2 h = *reinterpret_cast<__half2*>(&u);
    return __half22float2(h);
}

__device__ __forceinline__ void mma_f16(float c[4], const uint32_t a[4],
                                        const uint32_t b[2]) {
    asm volatile(
        "mma.sync.aligned.m16n8k16.row.col.f32.f16.f16.f32 "
        "{%0,%1,%2,%3}, {%4,%5,%6,%7}, {%8,%9}, {%0,%1,%2,%3};\n"
        : "+f"(c[0]), "+f"(c[1]), "+f"(c[2]), "+f"(c[3])
        : "r"(a[0]), "r"(a[1]), "r"(a[2]), "r"(a[3]), "r"(b[0]), "r"(b[1]));
}

__device__ __forceinline__ uint32_t smaddr(const void* p) {
    return (uint32_t)__cvta_generic_to_shared(p);
}
#define CP_ASYNC16(dst, src) \
    asm volatile("cp.async.cg.shared.global [%0], [%1], 16;" :: "r"(dst), "l"(src))
#define CP_COMMIT() asm volatile("cp.async.commit_group;")
#define CP_WAIT(n)  asm volatile("cp.async.wait_group %0;" :: "n"(n))

// ---------------------------------------------------------------------------
// conv: q,k,v -> fp16; weights -> fp16 packed along k.
// ---------------------------------------------------------------------------
__global__ __launch_bounds__(256) void conv_all(
    const float4* __restrict__ q, const float4* __restrict__ k,
    const float4* __restrict__ v,
    const float* __restrict__ wq, const float* __restrict__ wk,
    const float* __restrict__ wv, const float* __restrict__ wo,
    uint32_t* __restrict__ qh, uint32_t* __restrict__ kh,
    uint32_t* __restrict__ vh,
    uint32_t* __restrict__ wqp, uint32_t* __restrict__ wkp,
    uint32_t* __restrict__ wvp, uint32_t* __restrict__ wop)
{
    const int NQ4 = MROWS * DD / 4;       // 1048576 = 2^20
    const int NW4 = (DD/2) * DD / 4;      // 131072  = 2^17
    const int TOT = 3 * NQ4 + 4 * NW4;
    for (int i = blockIdx.x * 256 + threadIdx.x; i < TOT; i += gridDim.x * 256) {
        if (i < 3 * NQ4) {
            int s = i >> 20;
            int off = i & (NQ4 - 1);
            const float4* src = (s == 0) ? q : (s == 1) ? k : v;
            uint32_t* dst = (s == 0) ? qh : (s == 1) ? kh : vh;
            float4 x = src[off];
            uint2 u = {packh2(x.x, x.y), packh2(x.z, x.w)};
            *(uint2*)(dst + (size_t)off * 2) = u;
        } else {
            int j = i - 3 * NQ4;
            int s = j >> 17;
            int off = j & (NW4 - 1);
            const float* W = (s == 0) ? wq : (s == 1) ? wk : (s == 2) ? wv : wo;
            uint32_t* dst = (s == 0) ? wqp : (s == 1) ? wkp : (s == 2) ? wvp : wop;
            int kp_ = off >> 8;            // 0..511
            int n4 = (off & 255) * 4;      // col base
            float4 a = *(const float4*)(W + (size_t)(2 * kp_) * DD + n4);
            float4 b = *(const float4*)(W + (size_t)(2 * kp_ + 1) * DD + n4);
            uint4 o = {packh2(a.x, b.x), packh2(a.y, b.y),
                       packh2(a.z, b.z), packh2(a.w, b.w)};
            *(uint4*)(dst + (size_t)kp_ * DD + n4) = o;
        }
    }
}

// ---------------------------------------------------------------------------
// fp16 GEMM: C[4096,1024] = A @ W + bias. A fp16 [m][k] (u32 pairs), W packed.
// Block 128x128, BK=64 elems (32 u32), 2-stage cp.async. smem 71680 B.
// ---------------------------------------------------------------------------
template <bool F16OUT>
__device__ __forceinline__ void gemm16_core(
    const uint32_t* __restrict__ A, const uint32_t* __restrict__ Wp,
    const float* __restrict__ bias, void* __restrict__ Cout)
{
    extern __shared__ uint32_t dyn[];
    const int AST = 128 * 36;   // 32 used + 4 pad
    const int WST = 32 * 136;   // 32 k'-rows x 128 n + 8 pad
    const int STG = AST + WST;

    const int tid = threadIdx.x;
    const int lane = tid & 31;
    const int warp = tid >> 5;
    const int g = lane >> 2, t4 = lane & 3;
    const int warpM = warp >> 2, warpN = warp & 3;
    const int rowBase = blockIdx.y * 128;
    const int colBase = blockIdx.x * 128;
    const int mOff = warpM * 64, nOff = warpN * 32;

    auto prefetch = [&](int k0u, int s) {   // k0u in u32 (= k'-row) units
        uint32_t* As = dyn + s * STG;
        uint32_t* Ws = dyn + s * STG + AST;
#pragma unroll
        for (int i = 0; i < 4; i++) {       // A: 128 rows x 32 u32
            int l = tid + i * 256;
            int r = l >> 3, c = (l & 7) * 4;
            CP_ASYNC16(smaddr(&As[r * 36 + c]),
                       A + (size_t)(rowBase + r) * KU + k0u + c);
        }
#pragma unroll
        for (int i = 0; i < 4; i++) {       // W: 32 k'-rows x 128 n
            int l = tid + i * 256;
            int r = l >> 5, nc = (l & 31) * 4;
            CP_ASYNC16(smaddr(&Ws[r * 136 + nc]),
                       Wp + (size_t)(k0u + r) * DD + colBase + nc);
        }
    };

    float acc[4][4][4];
#pragma unroll
    for (int m = 0; m < 4; m++)
#pragma unroll
        for (int n = 0; n < 4; n++)
#pragma unroll
            for (int i = 0; i < 4; i++) acc[m][n][i] = 0.f;

    prefetch(0, 0);
    CP_COMMIT();

    int stage = 0;
    for (int k0u = 0; k0u < KU; k0u += 32) {   // 16 iters
        if (k0u + 32 < KU) {
            prefetch(k0u + 32, stage ^ 1);
            CP_COMMIT();
            CP_WAIT(1);
        } else {
            CP_WAIT(0);
        }
        __syncthreads();

        const uint32_t* As = dyn + stage * STG;
        const uint32_t* Ws = dyn + stage * STG + AST;
#pragma unroll
        for (int ks = 0; ks < 4; ks++) {       // 4 x k16
            int kb = ks * 8;
            uint32_t af[4][4], bf[4][2];
#pragma unroll
            for (int m = 0; m < 4; m++) {
                int mr = mOff + m * 16 + g;
                af[m][0] = As[mr * 36 + kb + t4];
                af[m][1] = As[(mr + 8) * 36 + kb + t4];
                af[m][2] = As[mr * 36 + kb + t4 + 4];
                af[m][3] = As[(mr + 8) * 36 + kb + t4 + 4];
            }
#pragma unroll
            for (int n = 0; n < 4; n++) {
                int nc = nOff + n * 8 + g;
                bf[n][0] = Ws[(kb + t4) * 136 + nc];
                bf[n][1] = Ws[(kb + t4 + 4) * 136 + nc];
            }
#pragma unroll
            for (int m = 0; m < 4; m++)
#pragma unroll
                for (int n = 0; n < 4; n++) mma_f16(acc[m][n], af[m], bf[n]);
        }
        stage ^= 1;
        __syncthreads();
    }

#pragma unroll
    for (int m = 0; m < 4; m++) {
        int r0 = rowBase + mOff + m * 16 + g;
#pragma unroll
        for (int n = 0; n < 4; n++) {
            int c0 = colBase + nOff + n * 8 + t4 * 2;
            float2 bv = *(const float2*)(bias + c0);
            float v00 = acc[m][n][0] + bv.x, v01 = acc[m][n][1] + bv.y;
            float v10 = acc[m][n][2] + bv.x, v11 = acc[m][n][3] + bv.y;
            if (F16OUT) {
                uint32_t* C = (uint32_t*)Cout;
                C[(size_t)r0 * KU + (c0 >> 1)] = packh2(v00, v01);
                C[(size_t)(r0 + 8) * KU + (c0 >> 1)] = packh2(v10, v11);
            } else {
                float* C = (float*)Cout;
                float2 o0 = {v00, v01}, o1 = {v10, v11};
                *(float2*)(C + (size_t)r0 * DD + c0) = o0;
                *(float2*)(C + (size_t)(r0 + 8) * DD + c0) = o1;
            }
        }
    }
}

__global__ __launch_bounds__(256, 2) void proj_qkv_tc(
    const uint32_t* __restrict__ qh, const uint32_t* __restrict__ kh,
    const uint32_t* __restrict__ vh,
    const uint32_t* __restrict__ wqp, const uint32_t* __restrict__ wkp,
    const uint32_t* __restrict__ wvp,
    const float* __restrict__ bq, const float* __restrict__ bk,
    const float* __restrict__ bv,
    uint32_t* __restrict__ qp, uint32_t* __restrict__ kp,
    uint32_t* __restrict__ vp)
{
    int z = blockIdx.z;
    const uint32_t* A = (z == 0) ? qh : (z == 1) ? kh : vh;
    const uint32_t* W = (z == 0) ? wqp : (z == 1) ? wkp : wvp;
    const float* B    = (z == 0) ? bq : (z == 1) ? bk : bv;
    uint32_t* C       = (z == 0) ? qp : (z == 1) ? kp : vp;
    gemm16_core<true>(A, W, B, C);
}

__global__ __launch_bounds__(256, 2) void out_proj_tc(
    const uint32_t* __restrict__ A, const uint32_t* __restrict__ W,
    const float* __restrict__ B, float* __restrict__ C)
{
    gemm16_core<false>(A, W, B, C);
}

// ---------------------------------------------------------------------------
// V head-transpose: vp fp16 [b][t][h*64+d] -> vpt [bh][d][t]
// ---------------------------------------------------------------------------
__global__ __launch_bounds__(256) void transpose_v(
    const uint32_t* __restrict__ vp, uint32_t* __restrict__ vpt)
{
    __shared__ uint16_t Ts[64][66];
    const int tid = threadIdx.x;
    const int bh = blockIdx.y, b = bh >> 4, h = bh & 15;
    const int t0 = blockIdx.x * 64;

#pragma unroll
    for (int i = 0; i < 8; i++) {
        int l = tid + i * 256;           // 2048 u32
        int r = l >> 5, c = l & 31;      // 32 u32 (64 d) per t-row
        uint32_t x = vp[(size_t)(b * SS + t0 + r) * KU + h * (DH/2) + c];
        *(uint32_t*)&Ts[r][2 * c] = x;
    }
    __syncthreads();
#pragma unroll
    for (int i = 0; i < 8; i++) {
        int l = tid + i * 256;
        int d = l >> 5, tc = l & 31;     // tc = u32 index along t (pairs)
        uint32_t lo = Ts[2 * tc][d];
        uint32_t hi = Ts[2 * tc + 1][d];
        vpt[(size_t)bh * DH * TU + (size_t)d * TU + (t0 >> 1) + tc] =
            lo | (hi << 16);
    }
}

// ---------------------------------------------------------------------------
// Logits fp16: x = 0.125*<q,k> + mask*-1e9; stores e = fp16(exp(x)) via smem
// staging (coalesced uint4 STG) + per-(row,warp-slice) sumexp partials.
// Dynamic smem 36864 B.
// ---------------------------------------------------------------------------
__global__ __launch_bounds__(256, 2) void logits16(
    const uint32_t* __restrict__ qp, const uint32_t* __restrict__ kp,
    const float* __restrict__ mask, uint32_t* __restrict__ e_out,
    float* __restrict__ part_l)
{
    extern __shared__ uint32_t dyn[];
    uint32_t* Qs = dyn;              // [128][36], 32 used
    uint32_t* Ks = dyn + 128 * 36;

    const int tid = threadIdx.x;
    const int lane = tid & 31;
    const int warp = tid >> 5;
    const int g = lane >> 2, t4 = lane & 3;
    const int warpM = warp >> 2, warpN = warp & 3;
    const int bh = blockIdx.z, b = bh >> 4, h = bh & 15;
    const int s0 = blockIdx.y * 128, t0 = blockIdx.x * 128;

    const uint32_t* qb = qp + (size_t)b * SS * KU + h * (DH/2);
    const uint32_t* kb = kp + (size_t)b * SS * KU + h * (DH/2);

#pragma unroll
    for (int i = 0; i < 4; i++) {
        int l = tid + i * 256;
        int r = l >> 3, dc = (l & 7) * 4;
        CP_ASYNC16(smaddr(&Qs[r * 36 + dc]), qb + (size_t)(s0 + r) * KU + dc);
        CP_ASYNC16(smaddr(&Ks[r * 36 + dc]), kb + (size_t)(t0 + r) * KU + dc);
    }
    CP_COMMIT();
    CP_WAIT(0);
    __syncthreads();

    float acc[4][4][4];
#pragma unroll
    for (int m = 0; m < 4; m++)
#pragma unroll
        for (int n = 0; n < 4; n++)
#pragma unroll
            for (int i = 0; i < 4; i++) acc[m][n][i] = 0.f;

#pragma unroll
    for (int ks = 0; ks < 4; ks++) {
        int kb_ = ks * 8;
        uint32_t af[4][4], bf[4][2];
#pragma unroll
        for (int m = 0; m < 4; m++) {
            int mr = warpM * 64 + m * 16 + g;
            af[m][0] = Qs[mr * 36 + kb_ + t4];
            af[m][1] = Qs[(mr + 8) * 36 + kb_ + t4];
            af[m][2] = Qs[mr * 36 + kb_ + t4 + 4];
            af[m][3] = Qs[(mr + 8) * 36 + kb_ + t4 + 4];
        }
#pragma unroll
        for (int n = 0; n < 4; n++) {
            int nr = warpN * 32 + n * 8 + g;
            bf[n][0] = Ks[nr * 36 + kb_ + t4];
            bf[n][1] = Ks[nr * 36 + kb_ + t4 + 4];
        }
#pragma unroll
        for (int m = 0; m < 4; m++)
#pragma unroll
            for (int n = 0; n < 4; n++) mma_f16(acc[m][n], af[m], bf[n]);
    }

    __syncthreads();                  // done with Qs/Ks
    uint32_t* Es = dyn;               // [128][68]

    float mk[4][2];
#pragma unroll
    for (int n = 0; n < 4; n++) {
        int lc = warpN * 32 + n * 8 + t4 * 2;
        float2 mv = *(const float2*)(mask + (size_t)b * SS + t0 + lc);
        mk[n][0] = mv.x * -1e9f;
        mk[n][1] = mv.y * -1e9f;
    }

    float rs[4][2];
#pragma unroll
    for (int m = 0; m < 4; m++) { rs[m][0] = 0.f; rs[m][1] = 0.f; }

#pragma unroll
    for (int m = 0; m < 4; m++) {
        int r = warpM * 64 + m * 16 + g;
        int cu = warpN * 16 + t4;     // u32 col within 64
#pragma unroll
        for (int n = 0; n < 4; n++) {
            float e0 = __expf(acc[m][n][0] * 0.125f + mk[n][0]);
            float e1 = __expf(acc[m][n][1] * 0.125f + mk[n][1]);
            float e2 = __expf(acc[m][n][2] * 0.125f + mk[n][0]);
            float e3 = __expf(acc[m][n][3] * 0.125f + mk[n][1]);
            uint32_t u01 = packh2(e0, e1), u23 = packh2(e2, e3);
            Es[r * 68 + cu + n * 4] = u01;
            Es[(r + 8) * 68 + cu + n * 4] = u23;
            float2 f01 = unpackh2(u01), f23 = unpackh2(u23);
            rs[m][0] += f01.x + f01.y;
            rs[m][1] += f23.x + f23.y;
        }
    }

#pragma unroll
    for (int m = 0; m < 4; m++)
#pragma unroll
        for (int hh = 0; hh < 2; hh++) {
            float s = rs[m][hh];
            s += __shfl_xor_sync(0xffffffffu, s, 1);
            s += __shfl_xor_sync(0xffffffffu, s, 2);
            if (t4 == 0) {
                int r = warpM * 64 + m * 16 + g + hh * 8;
                part_l[((size_t)bh * SS + s0 + r) * 64 + blockIdx.x * 4 + warpN] = s;
            }
        }
    __syncthreads();

    // coalesced copy Es -> e_out
#pragma unroll
    for (int i = 0; i < 8; i++) {
        int l = tid + i * 256;            // 2048 uint4
        int r = l >> 4, c4 = (l & 15) * 4;
        uint4 v = *(const uint4*)&Es[r * 68 + c4];
        *(uint4*)&e_out[((size_t)bh * SS + s0 + r) * TU + (t0 >> 1) + c4] = v;
    }
}

// ---------------------------------------------------------------------------
__global__ __launch_bounds__(256) void row_invl(
    const float4* __restrict__ pl, float* __restrict__ ril)
{
    int row = blockIdx.x * 256 + threadIdx.x;
    const float4* p = pl + (size_t)row * 16;
    float L = 0.f;
#pragma unroll
    for (int i = 0; i < 16; i++) {
        float4 v = p[i];
        L += (v.x + v.y) + (v.z + v.w);
    }
    ril[row] = 1.0f / L;
}

// ---------------------------------------------------------------------------
// ctx fp16: 128-row blocks, 4-stage cp.async, one sync/iter.
// A = e fp16 (direct cp.async), B = vpt fp16 (k-pairs contiguous along t).
// invL applied to accumulator in epilogue; p (fp32) written from smem e.
// Dynamic smem 61440 B: 4 x (As[128][20] + Vs[64][20]).
// ---------------------------------------------------------------------------
template <bool WRITEP>
__global__ __launch_bounds__(256, 3) void ctx16(
    const uint32_t* __restrict__ e_in, float* __restrict__ attn_out,
    const uint32_t* __restrict__ vpt, const float* __restrict__ rowIL,
    uint32_t* __restrict__ ctx)
{
    extern __shared__ uint32_t dynb[];
    const int ASZ = 128 * 20, VSZ = 64 * 20, STG4 = ASZ + VSZ;

    const int tid = threadIdx.x;
    const int lane = tid & 31;
    const int warp = tid >> 5;
    const int g = lane >> 2, t4 = lane & 3;
    const int warpM = warp >> 1, warpN = warp & 1;
    const int bh = blockIdx.y, b = bh >> 4, h = bh & 15;
    const int s0 = blockIdx.x * 128;

    const uint32_t* ae = e_in + (size_t)bh * SS * TU;
    const uint32_t* vb = vpt + (size_t)bh * DH * TU;

    // A loader: 128 rows x 4 uint4 (16 u32) -> 512 chunks, 2/thread
    const int ar = tid >> 2, ac4 = (tid & 3) * 4;
    // V loader: 64 rows x 4 uint4 -> 256 chunks, 1/thread
    const int vr = tid >> 2, vc4 = (tid & 3) * 4;

    float IL0 = 0.f, IL1 = 0.f;
    if (WRITEP) {
        IL0 = __ldg(rowIL + (size_t)bh * SS + s0 + ar);
        IL1 = __ldg(rowIL + (size_t)bh * SS + s0 + ar + 64);
    }

    auto prefetch = [&](int kt, int st) {
        uint32_t* As = dynb + st * STG4;
        uint32_t* Vs = dynb + st * STG4 + ASZ;
#pragma unroll
        for (int i = 0; i < 2; i++) {
            int r = ar + 64 * i;
            CP_ASYNC16(smaddr(&As[r * 20 + ac4]),
                       ae + (size_t)(s0 + r) * TU + kt * 16 + ac4);
        }
        if (tid < 256) {
            CP_ASYNC16(smaddr(&Vs[vr * 20 + vc4]),
                       vb + (size_t)vr * TU + kt * 16 + vc4);
        }
    };

    float acc[2][4][4];
#pragma unroll
    for (int m = 0; m < 2; m++)
#pragma unroll
        for (int n = 0; n < 4; n++)
#pragma unroll
            for (int i = 0; i < 4; i++) acc[m][n][i] = 0.f;

    prefetch(0, 0); CP_COMMIT();
    prefetch(1, 1); CP_COMMIT();
    prefetch(2, 2); CP_COMMIT();

    for (int kt = 0; kt < 64; kt++) {
        const int cur = kt & 3;
        if (kt <= 61) { CP_WAIT(2); }
        else if (kt == 62) { CP_WAIT(1); }
        else { CP_WAIT(0); }
        __syncthreads();
        if (kt + 3 < 64) { prefetch(kt + 3, (kt + 3) & 3); CP_COMMIT(); }

        const uint32_t* Ac = dynb + cur * STG4;
        const uint32_t* Vc = Ac + ASZ;
#pragma unroll
        for (int ks = 0; ks < 2; ks++) {
            int kb = ks * 8;
            uint32_t af[2][4], bf[4][2];
#pragma unroll
            for (int m = 0; m < 2; m++) {
                int mr = warpM * 32 + m * 16 + g;
                af[m][0] = Ac[mr * 20 + kb + t4];
                af[m][1] = Ac[(mr + 8) * 20 + kb + t4];
                af[m][2] = Ac[mr * 20 + kb + t4 + 4];
                af[m][3] = Ac[(mr + 8) * 20 + kb + t4 + 4];
            }
#pragma unroll
            for (int n = 0; n < 4; n++) {
                int nc = warpN * 32 + n * 8 + g;
                bf[n][0] = Vc[nc * 20 + kb + t4];
                bf[n][1] = Vc[nc * 20 + kb + t4 + 4];
            }
#pragma unroll
            for (int m = 0; m < 2; m++)
#pragma unroll
                for (int n = 0; n < 4; n++) mma_f16(acc[m][n], af[m], bf[n]);
        }

        if (WRITEP) {
#pragma unroll
            for (int i = 0; i < 2; i++) {
                int r = ar + 64 * i;
                float il = (i == 0) ? IL0 : IL1;
                float* orow = attn_out + ((size_t)bh * SS + s0 + r) * SS
                              + kt * 32 + ac4 * 2;
#pragma unroll
                for (int j = 0; j < 4; j += 2) {
                    float2 fa = unpackh2(Ac[r * 20 + ac4 + j]);
                    float2 fb = unpackh2(Ac[r * 20 + ac4 + j + 1]);
                    float4 o = {fa.x * il, fa.y * il, fb.x * il, fb.y * il};
                    *(float4*)(orow + j * 2) = o;
                }
            }
        }
    }

#pragma unroll
    for (int m = 0; m < 2; m++) {
        int r0 = warpM * 32 + m * 16 + g;
        float il0 = __ldg(rowIL + (size_t)bh * SS + s0 + r0);
        float il1 = __ldg(rowIL + (size_t)bh * SS + s0 + r0 + 8);
#pragma unroll
        for (int n = 0; n < 4; n++) {
            int c0 = warpN * 32 + n * 8 + t4 * 2;   // local col in 0..63
            uint32_t o0 = packh2(acc[m][n][0] * il0, acc[m][n][1] * il0);
            uint32_t o1 = packh2(acc[m][n][2] * il1, acc[m][n][3] * il1);
            ctx[((size_t)b * SS + s0 + r0) * KU + h * (DH/2) + (c0 >> 1)] = o0;
            ctx[((size_t)b * SS + s0 + r0 + 8) * KU + h * (DH/2) + (c0 >> 1)] = o1;
        }
    }
}

// ---------------------------------------------------------------------------
extern "C" void kernel_launch(void* const* d_in, const int* in_sizes, int n_in,
                              void* d_out, int out_size)
{
    const float* q    = (const float*)d_in[0];
    const float* k    = (const float*)d_in[1];
    const float* v    = (const float*)d_in[2];
    const float* mask = (const float*)d_in[3];
    const float* wq   = (const float*)d_in[4];
    const float* bq   = (const float*)d_in[5];
    const float* wk   = (const float*)d_in[6];
    const float* bk   = (const float*)d_in[7];
    const float* wv   = (const float*)d_in[8];
    const float* bv   = (const float*)d_in[9];
    const float* wo   = (const float*)d_in[10];
    const float* bo   = (const float*)d_in[11];
    float* out = (float*)d_out;

    uint32_t *qh, *kh, *vh, *wqp, *wkp, *wvp, *wop, *qp, *kp, *vp, *vpt, *ctx, *eb;
    float *pl, *ril;
    cudaGetSymbolAddress((void**)&qh,  g_qh);
    cudaGetSymbolAddress((void**)&kh,  g_kh);
    cudaGetSymbolAddress((void**)&vh,  g_vh);
    cudaGetSymbolAddress((void**)&wqp, g_wqp);
    cudaGetSymbolAddress((void**)&wkp, g_wkp);
    cudaGetSymbolAddress((void**)&wvp, g_wvp);
    cudaGetSymbolAddress((void**)&wop, g_wop);
    cudaGetSymbolAddress((void**)&qp,  g_qp);
    cudaGetSymbolAddress((void**)&kp,  g_kp);
    cudaGetSymbolAddress((void**)&vp,  g_vp);
    cudaGetSymbolAddress((void**)&vpt, g_vpt);
    cudaGetSymbolAddress((void**)&ctx, g_ctx);
    cudaGetSymbolAddress((void**)&eb,  g_e);
    cudaGetSymbolAddress((void**)&pl,  g_part_l);
    cudaGetSymbolAddress((void**)&ril, g_row_il);

    bool attn_in_out = ((size_t)out_size >= OUT_ELEMS + ATTN_ELEMS);
    float* attn_out = attn_in_out ? (out + OUT_ELEMS) : nullptr;

    const int DYN_G   = 2 * (128 * 36 + 32 * 136) * 4;   // 71680
    const int DYN_L   = 2 * (128 * 36) * 4;              // 36864
    const int DYN_CTX = 4 * (128 * 20 + 64 * 20) * 4;    // 61440
    cudaFuncSetAttribute(proj_qkv_tc, cudaFuncAttributeMaxDynamicSharedMemorySize, DYN_G);
    cudaFuncSetAttribute(out_proj_tc, cudaFuncAttributeMaxDynamicSharedMemorySize, DYN_G);
    cudaFuncSetAttribute(logits16,    cudaFuncAttributeMaxDynamicSharedMemorySize, DYN_L);
    cudaFuncSetAttribute(ctx16<true>,  cudaFuncAttributeMaxDynamicSharedMemorySize, DYN_CTX);
    cudaFuncSetAttribute(ctx16<false>, cudaFuncAttributeMaxDynamicSharedMemorySize, DYN_CTX);

    conv_all<<<2048, 256>>>(
        (const float4*)q, (const float4*)k, (const float4*)v,
        wq, wk, wv, wo,
        qh, kh, vh, wqp, wkp, wvp, wop);

    proj_qkv_tc<<<dim3(DD / 128, MROWS / 128, 3), 256, DYN_G>>>(
        qh, kh, vh, wqp, wkp, wvp, bq, bk, bv, qp, kp, vp);

    transpose_v<<<dim3(SS / 64, BB * HH), 256>>>(vp, vpt);

    logits16<<<dim3(SS / 128, SS / 128, BB * HH), 256, DYN_L>>>(
        qp, kp, mask, eb, pl);

    row_invl<<<NROWS_TOT / 256, 256>>>((const float4*)pl, ril);

    if (attn_in_out)
        ctx16<true><<<dim3(SS / 128, BB * HH), 256, DYN_CTX>>>(
            eb, attn_out, vpt, ril, ctx);
    else
        ctx16<false><<<dim3(SS / 128, BB * HH), 256, DYN_CTX>>>(
            eb, attn_out, vpt, ril, ctx);

    out_proj_tc<<<dim3(DD / 128, MROWS / 128), 256, DYN_G>>>(ctx, wop, bo, out);
}

// round 11
// speedup vs baseline: 1.5905x; 1.0278x over previous
#include <cuda_runtime.h>
#include <cuda_fp16.h>
#include <stdint.h>
#include <math.h>

#define BB 2
#define HH 16
#define SS 2048
#define DD 1024
#define DH 64
#define MROWS (BB*SS)          // 4096
#define NROWS_TOT (BB*HH*SS)   // 65536
#define KU 512                 // u32 (fp16x2) per DD row
#define TU 1024                // u32 (fp16x2) per SS row

static const size_t OUT_ELEMS  = (size_t)BB * SS * DD;        // 4,194,304
static const size_t ATTN_ELEMS = (size_t)BB * HH * SS * SS;   // 134,217,728

// Scratch (__device__ globals)
__device__ uint32_t g_qh[MROWS * KU];
__device__ uint32_t g_kh[MROWS * KU];
__device__ uint32_t g_vh[MROWS * KU];
__device__ uint32_t g_wqp[(DD/2) * DD];
__device__ uint32_t g_wkp[(DD/2) * DD];
__device__ uint32_t g_wvp[(DD/2) * DD];
__device__ uint32_t g_wop[(DD/2) * DD];
__device__ uint32_t g_qp[MROWS * KU];          // pre-scaled by 0.125
__device__ uint32_t g_kp[MROWS * KU];
__device__ uint32_t g_vp[MROWS * KU];
__device__ uint32_t g_vpt[(size_t)BB*HH*DH*TU];
__device__ uint32_t g_ctx[MROWS * KU];
__device__ uint32_t g_e[(size_t)BB*HH*SS*(SS/2)];
__device__ float g_part_l[(size_t)NROWS_TOT * 64];
__device__ float g_row_il[NROWS_TOT];

// ---------------------------------------------------------------------------
__device__ __forceinline__ uint32_t packh2(float a, float b) {
    __half2 h = __floats2half2_rn(a, b);
    return *reinterpret_cast<uint32_t*>(&h);
}
__device__ __forceinline__ float2 unpackh2(uint32_t u) {
    __half2 h = *reinterpret_cast<__half2*>(&u);
    return __half22float2(h);
}
__device__ __forceinline__ float ex2f(float x) {
    float y;
    asm("ex2.approx.ftz.f32 %0, %1;" : "=f"(y) : "f"(x));
    return y;
}

__device__ __forceinline__ void mma_f16(float c[4], const uint32_t a[4],
                                        const uint32_t b[2]) {
    asm volatile(
        "mma.sync.aligned.m16n8k16.row.col.f32.f16.f16.f32 "
        "{%0,%1,%2,%3}, {%4,%5,%6,%7}, {%8,%9}, {%0,%1,%2,%3};\n"
        : "+f"(c[0]), "+f"(c[1]), "+f"(c[2]), "+f"(c[3])
        : "r"(a[0]), "r"(a[1]), "r"(a[2]), "r"(a[3]), "r"(b[0]), "r"(b[1]));
}

__device__ __forceinline__ uint32_t smaddr(const void* p) {
    return (uint32_t)__cvta_generic_to_shared(p);
}
#define CP_ASYNC16(dst, src) \
    asm volatile("cp.async.cg.shared.global [%0], [%1], 16;" :: "r"(dst), "l"(src))
#define CP_COMMIT() asm volatile("cp.async.commit_group;")
#define CP_WAIT(n)  asm volatile("cp.async.wait_group %0;" :: "n"(n))

// ---------------------------------------------------------------------------
// conv: q,k,v -> fp16; weights -> fp16 packed along k.
// ---------------------------------------------------------------------------
__global__ __launch_bounds__(256) void conv_all(
    const float4* __restrict__ q, const float4* __restrict__ k,
    const float4* __restrict__ v,
    const float* __restrict__ wq, const float* __restrict__ wk,
    const float* __restrict__ wv, const float* __restrict__ wo,
    uint32_t* __restrict__ qh, uint32_t* __restrict__ kh,
    uint32_t* __restrict__ vh,
    uint32_t* __restrict__ wqp, uint32_t* __restrict__ wkp,
    uint32_t* __restrict__ wvp, uint32_t* __restrict__ wop)
{
    const int NQ4 = MROWS * DD / 4;       // 2^20
    const int NW4 = (DD/2) * DD / 4;      // 2^17
    const int TOT = 3 * NQ4 + 4 * NW4;
    for (int i = blockIdx.x * 256 + threadIdx.x; i < TOT; i += gridDim.x * 256) {
        if (i < 3 * NQ4) {
            int s = i >> 20;
            int off = i & (NQ4 - 1);
            const float4* src = (s == 0) ? q : (s == 1) ? k : v;
            uint32_t* dst = (s == 0) ? qh : (s == 1) ? kh : vh;
            float4 x = src[off];
            uint2 u = {packh2(x.x, x.y), packh2(x.z, x.w)};
            *(uint2*)(dst + (size_t)off * 2) = u;
        } else {
            int j = i - 3 * NQ4;
            int s = j >> 17;
            int off = j & (NW4 - 1);
            const float* W = (s == 0) ? wq : (s == 1) ? wk : (s == 2) ? wv : wo;
            uint32_t* dst = (s == 0) ? wqp : (s == 1) ? wkp : (s == 2) ? wvp : wop;
            int kp_ = off >> 8;
            int n4 = (off & 255) * 4;
            float4 a = *(const float4*)(W + (size_t)(2 * kp_) * DD + n4);
            float4 b = *(const float4*)(W + (size_t)(2 * kp_ + 1) * DD + n4);
            uint4 o = {packh2(a.x, b.x), packh2(a.y, b.y),
                       packh2(a.z, b.z), packh2(a.w, b.w)};
            *(uint4*)(dst + (size_t)kp_ * DD + n4) = o;
        }
    }
}

// ---------------------------------------------------------------------------
// fp16 GEMM: C = (A @ W + bias) * alpha. Block 128x128, BK=64, 2-stage.
// ---------------------------------------------------------------------------
template <bool F16OUT>
__device__ __forceinline__ void gemm16_core(
    const uint32_t* __restrict__ A, const uint32_t* __restrict__ Wp,
    const float* __restrict__ bias, void* __restrict__ Cout, float alpha)
{
    extern __shared__ uint32_t dyn[];
    const int AST = 128 * 36;
    const int WST = 32 * 136;
    const int STG = AST + WST;

    const int tid = threadIdx.x;
    const int lane = tid & 31;
    const int warp = tid >> 5;
    const int g = lane >> 2, t4 = lane & 3;
    const int warpM = warp >> 2, warpN = warp & 3;
    const int rowBase = blockIdx.y * 128;
    const int colBase = blockIdx.x * 128;
    const int mOff = warpM * 64, nOff = warpN * 32;

    auto prefetch = [&](int k0u, int s) {
        uint32_t* As = dyn + s * STG;
        uint32_t* Ws = dyn + s * STG + AST;
#pragma unroll
        for (int i = 0; i < 4; i++) {
            int l = tid + i * 256;
            int r = l >> 3, c = (l & 7) * 4;
            CP_ASYNC16(smaddr(&As[r * 36 + c]),
                       A + (size_t)(rowBase + r) * KU + k0u + c);
        }
#pragma unroll
        for (int i = 0; i < 4; i++) {
            int l = tid + i * 256;
            int r = l >> 5, nc = (l & 31) * 4;
            CP_ASYNC16(smaddr(&Ws[r * 136 + nc]),
                       Wp + (size_t)(k0u + r) * DD + colBase + nc);
        }
    };

    float acc[4][4][4];
#pragma unroll
    for (int m = 0; m < 4; m++)
#pragma unroll
        for (int n = 0; n < 4; n++)
#pragma unroll
            for (int i = 0; i < 4; i++) acc[m][n][i] = 0.f;

    prefetch(0, 0);
    CP_COMMIT();

    int stage = 0;
    for (int k0u = 0; k0u < KU; k0u += 32) {
        if (k0u + 32 < KU) {
            prefetch(k0u + 32, stage ^ 1);
            CP_COMMIT();
            CP_WAIT(1);
        } else {
            CP_WAIT(0);
        }
        __syncthreads();

        const uint32_t* As = dyn + stage * STG;
        const uint32_t* Ws = dyn + stage * STG + AST;
#pragma unroll
        for (int ks = 0; ks < 4; ks++) {
            int kb = ks * 8;
            uint32_t af[4][4], bf[4][2];
#pragma unroll
            for (int m = 0; m < 4; m++) {
                int mr = mOff + m * 16 + g;
                af[m][0] = As[mr * 36 + kb + t4];
                af[m][1] = As[(mr + 8) * 36 + kb + t4];
                af[m][2] = As[mr * 36 + kb + t4 + 4];
                af[m][3] = As[(mr + 8) * 36 + kb + t4 + 4];
            }
#pragma unroll
            for (int n = 0; n < 4; n++) {
                int nc = nOff + n * 8 + g;
                bf[n][0] = Ws[(kb + t4) * 136 + nc];
                bf[n][1] = Ws[(kb + t4 + 4) * 136 + nc];
            }
#pragma unroll
            for (int m = 0; m < 4; m++)
#pragma unroll
                for (int n = 0; n < 4; n++) mma_f16(acc[m][n], af[m], bf[n]);
        }
        stage ^= 1;
        __syncthreads();
    }

#pragma unroll
    for (int m = 0; m < 4; m++) {
        int r0 = rowBase + mOff + m * 16 + g;
#pragma unroll
        for (int n = 0; n < 4; n++) {
            int c0 = colBase + nOff + n * 8 + t4 * 2;
            float2 bv = *(const float2*)(bias + c0);
            float v00 = (acc[m][n][0] + bv.x) * alpha;
            float v01 = (acc[m][n][1] + bv.y) * alpha;
            float v10 = (acc[m][n][2] + bv.x) * alpha;
            float v11 = (acc[m][n][3] + bv.y) * alpha;
            if (F16OUT) {
                uint32_t* C = (uint32_t*)Cout;
                C[(size_t)r0 * KU + (c0 >> 1)] = packh2(v00, v01);
                C[(size_t)(r0 + 8) * KU + (c0 >> 1)] = packh2(v10, v11);
            } else {
                float* C = (float*)Cout;
                float2 o0 = {v00, v01}, o1 = {v10, v11};
                *(float2*)(C + (size_t)r0 * DD + c0) = o0;
                *(float2*)(C + (size_t)(r0 + 8) * DD + c0) = o1;
            }
        }
    }
}

__global__ __launch_bounds__(256, 2) void proj_qkv_tc(
    const uint32_t* __restrict__ qh, const uint32_t* __restrict__ kh,
    const uint32_t* __restrict__ vh,
    const uint32_t* __restrict__ wqp, const uint32_t* __restrict__ wkp,
    const uint32_t* __restrict__ wvp,
    const float* __restrict__ bq, const float* __restrict__ bk,
    const float* __restrict__ bv,
    uint32_t* __restrict__ qp, uint32_t* __restrict__ kp,
    uint32_t* __restrict__ vp)
{
    int z = blockIdx.z;
    const uint32_t* A = (z == 0) ? qh : (z == 1) ? kh : vh;
    const uint32_t* W = (z == 0) ? wqp : (z == 1) ? wkp : wvp;
    const float* B    = (z == 0) ? bq : (z == 1) ? bk : bv;
    uint32_t* C       = (z == 0) ? qp : (z == 1) ? kp : vp;
    float alpha       = (z == 0) ? 0.125f : 1.0f;   // fold softmax scale into Q
    gemm16_core<true>(A, W, B, C, alpha);
}

__global__ __launch_bounds__(256, 2) void out_proj_tc(
    const uint32_t* __restrict__ A, const uint32_t* __restrict__ W,
    const float* __restrict__ B, float* __restrict__ C)
{
    gemm16_core<false>(A, W, B, C, 1.0f);
}

// ---------------------------------------------------------------------------
// V head-transpose: vp fp16 [b][t][h*64+d] -> vpt [bh][d][t]
// ---------------------------------------------------------------------------
__global__ __launch_bounds__(256) void transpose_v(
    const uint32_t* __restrict__ vp, uint32_t* __restrict__ vpt)
{
    __shared__ uint16_t Ts[64][66];
    const int tid = threadIdx.x;
    const int bh = blockIdx.y, b = bh >> 4, h = bh & 15;
    const int t0 = blockIdx.x * 64;

#pragma unroll
    for (int i = 0; i < 8; i++) {
        int l = tid + i * 256;
        int r = l >> 5, c = l & 31;
        uint32_t x = vp[(size_t)(b * SS + t0 + r) * KU + h * (DH/2) + c];
        *(uint32_t*)&Ts[r][2 * c] = x;
    }
    __syncthreads();
#pragma unroll
    for (int i = 0; i < 8; i++) {
        int l = tid + i * 256;
        int d = l >> 5, tc = l & 31;
        uint32_t lo = Ts[2 * tc][d];
        uint32_t hi = Ts[2 * tc + 1][d];
        vpt[(size_t)bh * DH * TU + (size_t)d * TU + (t0 >> 1) + tc] =
            lo | (hi << 16);
    }
}

// ---------------------------------------------------------------------------
// Logits fp16: x = <q',k> (q' pre-scaled); e = fp16(ex2(x*log2e + mk2)).
// Es in DISJOINT smem (one less sync). Sums taken from f32 e directly.
// Dynamic smem 71680 B: Qs[128][36], Ks[128][36], Es[128][68].
// ---------------------------------------------------------------------------
__global__ __launch_bounds__(256, 2) void logits16(
    const uint32_t* __restrict__ qp, const uint32_t* __restrict__ kp,
    const float* __restrict__ mask, uint32_t* __restrict__ e_out,
    float* __restrict__ part_l)
{
    extern __shared__ uint32_t dyn[];
    uint32_t* Qs = dyn;                    // [128][36]
    uint32_t* Ks = dyn + 128 * 36;         // [128][36]
    uint32_t* Es = dyn + 2 * 128 * 36;     // [128][68]

    const int tid = threadIdx.x;
    const int lane = tid & 31;
    const int warp = tid >> 5;
    const int g = lane >> 2, t4 = lane & 3;
    const int warpM = warp >> 2, warpN = warp & 3;
    const int bh = blockIdx.z, b = bh >> 4, h = bh & 15;
    const int s0 = blockIdx.y * 128, t0 = blockIdx.x * 128;

    const uint32_t* qb = qp + (size_t)b * SS * KU + h * (DH/2);
    const uint32_t* kb = kp + (size_t)b * SS * KU + h * (DH/2);

#pragma unroll
    for (int i = 0; i < 4; i++) {
        int l = tid + i * 256;
        int r = l >> 3, dc = (l & 7) * 4;
        CP_ASYNC16(smaddr(&Qs[r * 36 + dc]), qb + (size_t)(s0 + r) * KU + dc);
        CP_ASYNC16(smaddr(&Ks[r * 36 + dc]), kb + (size_t)(t0 + r) * KU + dc);
    }
    CP_COMMIT();
    CP_WAIT(0);
    __syncthreads();

    float acc[4][4][4];
#pragma unroll
    for (int m = 0; m < 4; m++)
#pragma unroll
        for (int n = 0; n < 4; n++)
#pragma unroll
            for (int i = 0; i < 4; i++) acc[m][n][i] = 0.f;

#pragma unroll
    for (int ks = 0; ks < 4; ks++) {
        int kb_ = ks * 8;
        uint32_t af[4][4], bf[4][2];
#pragma unroll
        for (int m = 0; m < 4; m++) {
            int mr = warpM * 64 + m * 16 + g;
            af[m][0] = Qs[mr * 36 + kb_ + t4];
            af[m][1] = Qs[(mr + 8) * 36 + kb_ + t4];
            af[m][2] = Qs[mr * 36 + kb_ + t4 + 4];
            af[m][3] = Qs[(mr + 8) * 36 + kb_ + t4 + 4];
        }
#pragma unroll
        for (int n = 0; n < 4; n++) {
            int nr = warpN * 32 + n * 8 + g;
            bf[n][0] = Ks[nr * 36 + kb_ + t4];
            bf[n][1] = Ks[nr * 36 + kb_ + t4 + 4];
        }
#pragma unroll
        for (int m = 0; m < 4; m++)
#pragma unroll
            for (int n = 0; n < 4; n++) mma_f16(acc[m][n], af[m], bf[n]);
    }

    // mk2 = mask * (-1e9 * log2e); e = ex2(x*log2e + mk2)
    const float L2E = 1.44269504089f;
    float mk[4][2];
#pragma unroll
    for (int n = 0; n < 4; n++) {
        int lc = warpN * 32 + n * 8 + t4 * 2;
        float2 mv = *(const float2*)(mask + (size_t)b * SS + t0 + lc);
        mk[n][0] = mv.x * (-1e9f * L2E);
        mk[n][1] = mv.y * (-1e9f * L2E);
    }

    float rs[4][2];
#pragma unroll
    for (int m = 0; m < 4; m++) { rs[m][0] = 0.f; rs[m][1] = 0.f; }

#pragma unroll
    for (int m = 0; m < 4; m++) {
        int r = warpM * 64 + m * 16 + g;
        int cu = warpN * 16 + t4;
#pragma unroll
        for (int n = 0; n < 4; n++) {
            float e0 = ex2f(fmaf(acc[m][n][0], L2E, mk[n][0]));
            float e1 = ex2f(fmaf(acc[m][n][1], L2E, mk[n][1]));
            float e2 = ex2f(fmaf(acc[m][n][2], L2E, mk[n][0]));
            float e3 = ex2f(fmaf(acc[m][n][3], L2E, mk[n][1]));
            Es[r * 68 + cu + n * 4] = packh2(e0, e1);
            Es[(r + 8) * 68 + cu + n * 4] = packh2(e2, e3);
            rs[m][0] += e0 + e1;
            rs[m][1] += e2 + e3;
        }
    }

#pragma unroll
    for (int m = 0; m < 4; m++)
#pragma unroll
        for (int hh = 0; hh < 2; hh++) {
            float s = rs[m][hh];
            s += __shfl_xor_sync(0xffffffffu, s, 1);
            s += __shfl_xor_sync(0xffffffffu, s, 2);
            if (t4 == 0) {
                int r = warpM * 64 + m * 16 + g + hh * 8;
                part_l[((size_t)bh * SS + s0 + r) * 64 + blockIdx.x * 4 + warpN] = s;
            }
        }
    __syncthreads();

    // coalesced copy Es -> e_out
#pragma unroll
    for (int i = 0; i < 8; i++) {
        int l = tid + i * 256;
        int r = l >> 4, c4 = (l & 15) * 4;
        uint4 v = *(const uint4*)&Es[r * 68 + c4];
        *(uint4*)&e_out[((size_t)bh * SS + s0 + r) * TU + (t0 >> 1) + c4] = v;
    }
}

// ---------------------------------------------------------------------------
// row_invl: 8 threads per row (2 float4 each), shfl reduce.
// Block covers 32 rows -> grid must be NROWS_TOT/32 = 2048.
// ---------------------------------------------------------------------------
__global__ __launch_bounds__(256) void row_invl(
    const float4* __restrict__ pl, float* __restrict__ ril)
{
    const int warp = threadIdx.x >> 5;
    const int lane = threadIdx.x & 31;
    const int riw = lane >> 3, t8 = lane & 7;
    const int row = blockIdx.x * 32 + warp * 4 + riw;
    const float4* p = pl + (size_t)row * 16 + t8 * 2;
    float4 a = p[0], b = p[1];
    float L = (a.x + a.y) + (a.z + a.w) + (b.x + b.y) + (b.z + b.w);
    L += __shfl_xor_sync(0xffffffffu, L, 1);
    L += __shfl_xor_sync(0xffffffffu, L, 2);
    L += __shfl_xor_sync(0xffffffffu, L, 4);
    if (t8 == 0) ril[row] = 1.0f / L;
}

// ---------------------------------------------------------------------------
// ctx fp16: 128-row blocks, 4-stage cp.async, one sync/iter.
// ---------------------------------------------------------------------------
template <bool WRITEP>
__global__ __launch_bounds__(256, 3) void ctx16(
    const uint32_t* __restrict__ e_in, float* __restrict__ attn_out,
    const uint32_t* __restrict__ vpt, const float* __restrict__ rowIL,
    uint32_t* __restrict__ ctx)
{
    extern __shared__ uint32_t dynb[];
    const int ASZ = 128 * 20, VSZ = 64 * 20, STG4 = ASZ + VSZ;

    const int tid = threadIdx.x;
    const int lane = tid & 31;
    const int warp = tid >> 5;
    const int g = lane >> 2, t4 = lane & 3;
    const int warpM = warp >> 1, warpN = warp & 1;
    const int bh = blockIdx.y, b = bh >> 4, h = bh & 15;
    const int s0 = blockIdx.x * 128;

    const uint32_t* ae = e_in + (size_t)bh * SS * TU;
    const uint32_t* vb = vpt + (size_t)bh * DH * TU;

    const int ar = tid >> 2, ac4 = (tid & 3) * 4;
    const int vr = tid >> 2, vc4 = (tid & 3) * 4;

    float IL0 = 0.f, IL1 = 0.f;
    if (WRITEP) {
        IL0 = __ldg(rowIL + (size_t)bh * SS + s0 + ar);
        IL1 = __ldg(rowIL + (size_t)bh * SS + s0 + ar + 64);
    }

    auto prefetch = [&](int kt, int st) {
        uint32_t* As = dynb + st * STG4;
        uint32_t* Vs = dynb + st * STG4 + ASZ;
#pragma unroll
        for (int i = 0; i < 2; i++) {
            int r = ar + 64 * i;
            CP_ASYNC16(smaddr(&As[r * 20 + ac4]),
                       ae + (size_t)(s0 + r) * TU + kt * 16 + ac4);
        }
        if (vr < 64) {
            CP_ASYNC16(smaddr(&Vs[vr * 20 + vc4]),
                       vb + (size_t)vr * TU + kt * 16 + vc4);
        }
    };

    float acc[2][4][4];
#pragma unroll
    for (int m = 0; m < 2; m++)
#pragma unroll
        for (int n = 0; n < 4; n++)
#pragma unroll
            for (int i = 0; i < 4; i++) acc[m][n][i] = 0.f;

    prefetch(0, 0); CP_COMMIT();
    prefetch(1, 1); CP_COMMIT();
    prefetch(2, 2); CP_COMMIT();

    for (int kt = 0; kt < 64; kt++) {
        const int cur = kt & 3;
        if (kt <= 61) { CP_WAIT(2); }
        else if (kt == 62) { CP_WAIT(1); }
        else { CP_WAIT(0); }
        __syncthreads();
        if (kt + 3 < 64) { prefetch(kt + 3, (kt + 3) & 3); CP_COMMIT(); }

        const uint32_t* Ac = dynb + cur * STG4;
        const uint32_t* Vc = Ac + ASZ;
#pragma unroll
        for (int ks = 0; ks < 2; ks++) {
            int kb = ks * 8;
            uint32_t af[2][4], bf[4][2];
#pragma unroll
            for (int m = 0; m < 2; m++) {
                int mr = warpM * 32 + m * 16 + g;
                af[m][0] = Ac[mr * 20 + kb + t4];
                af[m][1] = Ac[(mr + 8) * 20 + kb + t4];
                af[m][2] = Ac[mr * 20 + kb + t4 + 4];
                af[m][3] = Ac[(mr + 8) * 20 + kb + t4 + 4];
            }
#pragma unroll
            for (int n = 0; n < 4; n++) {
                int nc = warpN * 32 + n * 8 + g;
                bf[n][0] = Vc[nc * 20 + kb + t4];
                bf[n][1] = Vc[nc * 20 + kb + t4 + 4];
            }
#pragma unroll
            for (int m = 0; m < 2; m++)
#pragma unroll
                for (int n = 0; n < 4; n++) mma_f16(acc[m][n], af[m], bf[n]);
        }

        if (WRITEP) {
#pragma unroll
            for (int i = 0; i < 2; i++) {
                int r = ar + 64 * i;
                float il = (i == 0) ? IL0 : IL1;
                float* orow = attn_out + ((size_t)bh * SS + s0 + r) * SS
                              + kt * 32 + ac4 * 2;
#pragma unroll
                for (int j = 0; j < 4; j += 2) {
                    float2 fa = unpackh2(Ac[r * 20 + ac4 + j]);
                    float2 fb = unpackh2(Ac[r * 20 + ac4 + j + 1]);
                    float4 o = {fa.x * il, fa.y * il, fb.x * il, fb.y * il};
                    *(float4*)(orow + j * 2) = o;
                }
            }
        }
    }

#pragma unroll
    for (int m = 0; m < 2; m++) {
        int r0 = warpM * 32 + m * 16 + g;
        float il0 = __ldg(rowIL + (size_t)bh * SS + s0 + r0);
        float il1 = __ldg(rowIL + (size_t)bh * SS + s0 + r0 + 8);
#pragma unroll
        for (int n = 0; n < 4; n++) {
            int c0 = warpN * 32 + n * 8 + t4 * 2;
            uint32_t o0 = packh2(acc[m][n][0] * il0, acc[m][n][1] * il0);
            uint32_t o1 = packh2(acc[m][n][2] * il1, acc[m][n][3] * il1);
            ctx[((size_t)b * SS + s0 + r0) * KU + h * (DH/2) + (c0 >> 1)] = o0;
            ctx[((size_t)b * SS + s0 + r0 + 8) * KU + h * (DH/2) + (c0 >> 1)] = o1;
        }
    }
}

// ---------------------------------------------------------------------------
extern "C" void kernel_launch(void* const* d_in, const int* in_sizes, int n_in,
                              void* d_out, int out_size)
{
    const float* q    = (const float*)d_in[0];
    const float* k    = (const float*)d_in[1];
    const float* v    = (const float*)d_in[2];
    const float* mask = (const float*)d_in[3];
    const float* wq   = (const float*)d_in[4];
    const float* bq   = (const float*)d_in[5];
    const float* wk   = (const float*)d_in[6];
    const float* bk   = (const float*)d_in[7];
    const float* wv   = (const float*)d_in[8];
    const float* bv   = (const float*)d_in[9];
    const float* wo   = (const float*)d_in[10];
    const float* bo   = (const float*)d_in[11];
    float* out = (float*)d_out;

    uint32_t *qh, *kh, *vh, *wqp, *wkp, *wvp, *wop, *qp, *kp, *vp, *vpt, *ctx, *eb;
    float *pl, *ril;
    cudaGetSymbolAddress((void**)&qh,  g_qh);
    cudaGetSymbolAddress((void**)&kh,  g_kh);
    cudaGetSymbolAddress((void**)&vh,  g_vh);
    cudaGetSymbolAddress((void**)&wqp, g_wqp);
    cudaGetSymbolAddress((void**)&wkp, g_wkp);
    cudaGetSymbolAddress((void**)&wvp, g_wvp);
    cudaGetSymbolAddress((void**)&wop, g_wop);
    cudaGetSymbolAddress((void**)&qp,  g_qp);
    cudaGetSymbolAddress((void**)&kp,  g_kp);
    cudaGetSymbolAddress((void**)&vp,  g_vp);
    cudaGetSymbolAddress((void**)&vpt, g_vpt);
    cudaGetSymbolAddress((void**)&ctx, g_ctx);
    cudaGetSymbolAddress((void**)&eb,  g_e);
    cudaGetSymbolAddress((void**)&pl,  g_part_l);
    cudaGetSymbolAddress((void**)&ril, g_row_il);

    bool attn_in_out = ((size_t)out_size >= OUT_ELEMS + ATTN_ELEMS);
    float* attn_out = attn_in_out ? (out + OUT_ELEMS) : nullptr;

    const int DYN_G   = 2 * (128 * 36 + 32 * 136) * 4;       // 71680
    const int DYN_L   = (2 * 128 * 36 + 128 * 68) * 4;       // 71680
    const int DYN_CTX = 4 * (128 * 20 + 64 * 20) * 4;        // 61440
    cudaFuncSetAttribute(proj_qkv_tc, cudaFuncAttributeMaxDynamicSharedMemorySize, DYN_G);
    cudaFuncSetAttribute(out_proj_tc, cudaFuncAttributeMaxDynamicSharedMemorySize, DYN_G);
    cudaFuncSetAttribute(logits16,    cudaFuncAttributeMaxDynamicSharedMemorySize, DYN_L);
    cudaFuncSetAttribute(ctx16<true>,  cudaFuncAttributeMaxDynamicSharedMemorySize, DYN_CTX);
    cudaFuncSetAttribute(ctx16<false>, cudaFuncAttributeMaxDynamicSharedMemorySize, DYN_CTX);

    conv_all<<<2048, 256>>>(
        (const float4*)q, (const float4*)k, (const float4*)v,
        wq, wk, wv, wo,
        qh, kh, vh, wqp, wkp, wvp, wop);

    proj_qkv_tc<<<dim3(DD / 128, MROWS / 128, 3), 256, DYN_G>>>(
        qh, kh, vh, wqp, wkp, wvp, bq, bk, bv, qp, kp, vp);

    transpose_v<<<dim3(SS / 64, BB * HH), 256>>>(vp, vpt);

    logits16<<<dim3(SS / 128, SS / 128, BB * HH), 256, DYN_L>>>(
        qp, kp, mask, eb, pl);

    row_invl<<<NROWS_TOT / 32, 256>>>((const float4*)pl, ril);   // FIXED grid

    if (attn_in_out)
        ctx16<true><<<dim3(SS / 128, BB * HH), 256, DYN_CTX>>>(
            eb, attn_out, vpt, ril, ctx);
    else
        ctx16<false><<<dim3(SS / 128, BB * HH), 256, DYN_CTX>>>(
            eb, attn_out, vpt, ril, ctx);

    out_proj_tc<<<dim3(DD / 128, MROWS / 128), 256, DYN_G>>>(ctx, wop, bo, out);
}

// round 12
// speedup vs baseline: 1.8801x; 1.1821x over previous
#include <cuda_runtime.h>
#include <cuda_fp16.h>
#include <stdint.h>
#include <math.h>

#define BB 2
#define HH 16
#define SS 2048
#define DD 1024
#define DH 64
#define MROWS (BB*SS)          // 4096
#define KU 512                 // u32 (fp16x2) per DD row
#define TU 1024                // u32 (fp16x2) per SS row

static const size_t OUT_ELEMS  = (size_t)BB * SS * DD;        // 4,194,304
static const size_t ATTN_ELEMS = (size_t)BB * HH * SS * SS;   // 134,217,728

// Scratch (__device__ globals)
__device__ uint32_t g_qh[MROWS * KU];
__device__ uint32_t g_kh[MROWS * KU];
__device__ uint32_t g_vh[MROWS * KU];
__device__ uint32_t g_wqp[(DD/2) * DD];
__device__ uint32_t g_wkp[(DD/2) * DD];
__device__ uint32_t g_wvp[(DD/2) * DD];
__device__ uint32_t g_wop[(DD/2) * DD];
__device__ uint32_t g_qp[MROWS * KU];          // pre-scaled by 0.125
__device__ uint32_t g_kp[MROWS * KU];
__device__ uint32_t g_vp[MROWS * KU];
__device__ uint32_t g_vpt[(size_t)BB*HH*DH*TU];
__device__ uint32_t g_ctx[MROWS * KU];

// ---------------------------------------------------------------------------
__device__ __forceinline__ uint32_t packh2(float a, float b) {
    __half2 h = __floats2half2_rn(a, b);
    return *reinterpret_cast<uint32_t*>(&h);
}
__device__ __forceinline__ float ex2f(float x) {
    float y;
    asm("ex2.approx.ftz.f32 %0, %1;" : "=f"(y) : "f"(x));
    return y;
}

__device__ __forceinline__ void mma_f16(float c[4], const uint32_t a[4],
                                        const uint32_t b[2]) {
    asm volatile(
        "mma.sync.aligned.m16n8k16.row.col.f32.f16.f16.f32 "
        "{%0,%1,%2,%3}, {%4,%5,%6,%7}, {%8,%9}, {%0,%1,%2,%3};\n"
        : "+f"(c[0]), "+f"(c[1]), "+f"(c[2]), "+f"(c[3])
        : "r"(a[0]), "r"(a[1]), "r"(a[2]), "r"(a[3]), "r"(b[0]), "r"(b[1]));
}

__device__ __forceinline__ uint32_t smaddr(const void* p) {
    return (uint32_t)__cvta_generic_to_shared(p);
}
#define CP_ASYNC16(dst, src) \
    asm volatile("cp.async.cg.shared.global [%0], [%1], 16;" :: "r"(dst), "l"(src))
#define CP_COMMIT() asm volatile("cp.async.commit_group;")
#define CP_WAIT(n)  asm volatile("cp.async.wait_group %0;" :: "n"(n))

// ---------------------------------------------------------------------------
// conv: q,k,v -> fp16; weights -> fp16 packed along k.
// ---------------------------------------------------------------------------
__global__ __launch_bounds__(256) void conv_all(
    const float4* __restrict__ q, const float4* __restrict__ k,
    const float4* __restrict__ v,
    const float* __restrict__ wq, const float* __restrict__ wk,
    const float* __restrict__ wv, const float* __restrict__ wo,
    uint32_t* __restrict__ qh, uint32_t* __restrict__ kh,
    uint32_t* __restrict__ vh,
    uint32_t* __restrict__ wqp, uint32_t* __restrict__ wkp,
    uint32_t* __restrict__ wvp, uint32_t* __restrict__ wop)
{
    const int NQ4 = MROWS * DD / 4;       // 2^20
    const int NW4 = (DD/2) * DD / 4;      // 2^17
    const int TOT = 3 * NQ4 + 4 * NW4;
    for (int i = blockIdx.x * 256 + threadIdx.x; i < TOT; i += gridDim.x * 256) {
        if (i < 3 * NQ4) {
            int s = i >> 20;
            int off = i & (NQ4 - 1);
            const float4* src = (s == 0) ? q : (s == 1) ? k : v;
            uint32_t* dst = (s == 0) ? qh : (s == 1) ? kh : vh;
            float4 x = src[off];
            uint2 u = {packh2(x.x, x.y), packh2(x.z, x.w)};
            *(uint2*)(dst + (size_t)off * 2) = u;
        } else {
            int j = i - 3 * NQ4;
            int s = j >> 17;
            int off = j & (NW4 - 1);
            const float* W = (s == 0) ? wq : (s == 1) ? wk : (s == 2) ? wv : wo;
            uint32_t* dst = (s == 0) ? wqp : (s == 1) ? wkp : (s == 2) ? wvp : wop;
            int kp_ = off >> 8;
            int n4 = (off & 255) * 4;
            float4 a = *(const float4*)(W + (size_t)(2 * kp_) * DD + n4);
            float4 b = *(const float4*)(W + (size_t)(2 * kp_ + 1) * DD + n4);
            uint4 o = {packh2(a.x, b.x), packh2(a.y, b.y),
                       packh2(a.z, b.z), packh2(a.w, b.w)};
            *(uint4*)(dst + (size_t)kp_ * DD + n4) = o;
        }
    }
}

// ---------------------------------------------------------------------------
// fp16 GEMM: C = (A @ W + bias) * alpha. Block 128x128, BK=64, 2-stage.
// ---------------------------------------------------------------------------
template <bool F16OUT>
__device__ __forceinline__ void gemm16_core(
    const uint32_t* __restrict__ A, const uint32_t* __restrict__ Wp,
    const float* __restrict__ bias, void* __restrict__ Cout, float alpha)
{
    extern __shared__ uint32_t dyn[];
    const int AST = 128 * 36;
    const int WST = 32 * 136;
    const int STG = AST + WST;

    const int tid = threadIdx.x;
    const int lane = tid & 31;
    const int warp = tid >> 5;
    const int g = lane >> 2, t4 = lane & 3;
    const int warpM = warp >> 2, warpN = warp & 3;
    const int rowBase = blockIdx.y * 128;
    const int colBase = blockIdx.x * 128;
    const int mOff = warpM * 64, nOff = warpN * 32;

    auto prefetch = [&](int k0u, int s) {
        uint32_t* As = dyn + s * STG;
        uint32_t* Ws = dyn + s * STG + AST;
#pragma unroll
        for (int i = 0; i < 4; i++) {
            int l = tid + i * 256;
            int r = l >> 3, c = (l & 7) * 4;
            CP_ASYNC16(smaddr(&As[r * 36 + c]),
                       A + (size_t)(rowBase + r) * KU + k0u + c);
        }
#pragma unroll
        for (int i = 0; i < 4; i++) {
            int l = tid + i * 256;
            int r = l >> 5, nc = (l & 31) * 4;
            CP_ASYNC16(smaddr(&Ws[r * 136 + nc]),
                       Wp + (size_t)(k0u + r) * DD + colBase + nc);
        }
    };

    float acc[4][4][4];
#pragma unroll
    for (int m = 0; m < 4; m++)
#pragma unroll
        for (int n = 0; n < 4; n++)
#pragma unroll
            for (int i = 0; i < 4; i++) acc[m][n][i] = 0.f;

    prefetch(0, 0);
    CP_COMMIT();

    int stage = 0;
    for (int k0u = 0; k0u < KU; k0u += 32) {
        if (k0u + 32 < KU) {
            prefetch(k0u + 32, stage ^ 1);
            CP_COMMIT();
            CP_WAIT(1);
        } else {
            CP_WAIT(0);
        }
        __syncthreads();

        const uint32_t* As = dyn + stage * STG;
        const uint32_t* Ws = dyn + stage * STG + AST;
#pragma unroll
        for (int ks = 0; ks < 4; ks++) {
            int kb = ks * 8;
            uint32_t af[4][4], bf[4][2];
#pragma unroll
            for (int m = 0; m < 4; m++) {
                int mr = mOff + m * 16 + g;
                af[m][0] = As[mr * 36 + kb + t4];
                af[m][1] = As[(mr + 8) * 36 + kb + t4];
                af[m][2] = As[mr * 36 + kb + t4 + 4];
                af[m][3] = As[(mr + 8) * 36 + kb + t4 + 4];
            }
#pragma unroll
            for (int n = 0; n < 4; n++) {
                int nc = nOff + n * 8 + g;
                bf[n][0] = Ws[(kb + t4) * 136 + nc];
                bf[n][1] = Ws[(kb + t4 + 4) * 136 + nc];
            }
#pragma unroll
            for (int m = 0; m < 4; m++)
#pragma unroll
                for (int n = 0; n < 4; n++) mma_f16(acc[m][n], af[m], bf[n]);
        }
        stage ^= 1;
        __syncthreads();
    }

#pragma unroll
    for (int m = 0; m < 4; m++) {
        int r0 = rowBase + mOff + m * 16 + g;
#pragma unroll
        for (int n = 0; n < 4; n++) {
            int c0 = colBase + nOff + n * 8 + t4 * 2;
            float2 bv = *(const float2*)(bias + c0);
            float v00 = (acc[m][n][0] + bv.x) * alpha;
            float v01 = (acc[m][n][1] + bv.y) * alpha;
            float v10 = (acc[m][n][2] + bv.x) * alpha;
            float v11 = (acc[m][n][3] + bv.y) * alpha;
            if (F16OUT) {
                uint32_t* C = (uint32_t*)Cout;
                C[(size_t)r0 * KU + (c0 >> 1)] = packh2(v00, v01);
                C[(size_t)(r0 + 8) * KU + (c0 >> 1)] = packh2(v10, v11);
            } else {
                float* C = (float*)Cout;
                float2 o0 = {v00, v01}, o1 = {v10, v11};
                *(float2*)(C + (size_t)r0 * DD + c0) = o0;
                *(float2*)(C + (size_t)(r0 + 8) * DD + c0) = o1;
            }
        }
    }
}

__global__ __launch_bounds__(256, 2) void proj_qkv_tc(
    const uint32_t* __restrict__ qh, const uint32_t* __restrict__ kh,
    const uint32_t* __restrict__ vh,
    const uint32_t* __restrict__ wqp, const uint32_t* __restrict__ wkp,
    const uint32_t* __restrict__ wvp,
    const float* __restrict__ bq, const float* __restrict__ bk,
    const float* __restrict__ bv,
    uint32_t* __restrict__ qp, uint32_t* __restrict__ kp,
    uint32_t* __restrict__ vp)
{
    int z = blockIdx.z;
    const uint32_t* A = (z == 0) ? qh : (z == 1) ? kh : vh;
    const uint32_t* W = (z == 0) ? wqp : (z == 1) ? wkp : wvp;
    const float* B    = (z == 0) ? bq : (z == 1) ? bk : bv;
    uint32_t* C       = (z == 0) ? qp : (z == 1) ? kp : vp;
    float alpha       = (z == 0) ? 0.125f : 1.0f;
    gemm16_core<true>(A, W, B, C, alpha);
}

__global__ __launch_bounds__(256, 2) void out_proj_tc(
    const uint32_t* __restrict__ A, const uint32_t* __restrict__ W,
    const float* __restrict__ B, float* __restrict__ C)
{
    gemm16_core<false>(A, W, B, C, 1.0f);
}

// ---------------------------------------------------------------------------
// V head-transpose: vp fp16 [b][t][h*64+d] -> vpt [bh][d][t]
// ---------------------------------------------------------------------------
__global__ __launch_bounds__(256) void transpose_v(
    const uint32_t* __restrict__ vp, uint32_t* __restrict__ vpt)
{
    __shared__ uint16_t Ts[64][66];
    const int tid = threadIdx.x;
    const int bh = blockIdx.y, b = bh >> 4, h = bh & 15;
    const int t0 = blockIdx.x * 64;

#pragma unroll
    for (int i = 0; i < 8; i++) {
        int l = tid + i * 256;
        int r = l >> 5, c = l & 31;
        uint32_t x = vp[(size_t)(b * SS + t0 + r) * KU + h * (DH/2) + c];
        *(uint32_t*)&Ts[r][2 * c] = x;
    }
    __syncthreads();
#pragma unroll
    for (int i = 0; i < 8; i++) {
        int l = tid + i * 256;
        int d = l >> 5, tc = l & 31;
        uint32_t lo = Ts[2 * tc][d];
        uint32_t hi = Ts[2 * tc + 1][d];
        vpt[(size_t)bh * DH * TU + (size_t)d * TU + (t0 >> 1) + tc] =
            lo | (hi << 16);
    }
}

// ---------------------------------------------------------------------------
// Fused attention: per block 128 s-rows of one (b,h). Two passes over K.
// Pass 1: x = Q'K^T, e = ex2(x*L2E + mk), row-sums -> invL (block-local).
// Pass 2: recompute e, write p = e*invL to attn_out, feed e-fragments
// directly into PV MMA (C-frag -> A-frag register reuse). ctx = accv*invL.
// Warp = 16 s-rows x full t. Q hoisted to registers.
// Dyn smem: msk[2048]f32 + ILs[128]f32 + 2 x (K[128][36] + V[64][68]) u32.
// ---------------------------------------------------------------------------
template <bool WRITEP>
__global__ __launch_bounds__(256, 2) void attn_fused(
    const uint32_t* __restrict__ qp, const uint32_t* __restrict__ kp,
    const uint32_t* __restrict__ vpt, const float* __restrict__ mask,
    float* __restrict__ attn_out, uint32_t* __restrict__ ctx)
{
    extern __shared__ uint32_t dynf[];
    float* msk = (float*)dynf;                 // [2048]
    float* ILs = (float*)(dynf + SS);          // [128]
    uint32_t* stg = dynf + SS + 128;           // 2 stages
    const int KSZ = 128 * 36, VSZ = 64 * 68, STG = KSZ + VSZ;

    const int tid = threadIdx.x;
    const int lane = tid & 31;
    const int warp = tid >> 5;
    const int g = lane >> 2, t4 = lane & 3;
    const int bh = blockIdx.y, b = bh >> 4, h = bh & 15;
    const int s0 = blockIdx.x * 128;
    const float L2E = 1.44269504089f;

    const uint32_t* qb = qp + (size_t)b * SS * KU + h * 32;
    const uint32_t* kb = kp + (size_t)b * SS * KU + h * 32;
    const uint32_t* vb = vpt + (size_t)bh * DH * TU;

    // mask -> smem, pre-scaled by -1e9*log2e
    for (int i = tid; i < SS; i += 256)
        msk[i] = mask[(size_t)b * SS + i] * (-1e9f * L2E);

    // Q -> stage0 area -> registers (held for whole kernel)
    {
        uint32_t* Qs = stg;
#pragma unroll
        for (int i = 0; i < 4; i++) {
            int l = tid + i * 256;
            int r = l >> 3, c = (l & 7) * 4;
            CP_ASYNC16(smaddr(&Qs[r * 36 + c]), qb + (size_t)(s0 + r) * KU + c);
        }
        CP_COMMIT(); CP_WAIT(0);
        __syncthreads();
    }
    uint32_t qf[4][4];
    {
        const uint32_t* Qs = stg;
        int mr = warp * 16 + g;
#pragma unroll
        for (int kt = 0; kt < 4; kt++) {
            qf[kt][0] = Qs[mr * 36 + kt * 8 + t4];
            qf[kt][1] = Qs[(mr + 8) * 36 + kt * 8 + t4];
            qf[kt][2] = Qs[mr * 36 + kt * 8 + t4 + 4];
            qf[kt][3] = Qs[(mr + 8) * 36 + kt * 8 + t4 + 4];
        }
    }
    __syncthreads();   // all warps own Q before stage reuse

    auto prefK = [&](int it, int st) {
        uint32_t* Ks = stg + st * STG;
#pragma unroll
        for (int i = 0; i < 4; i++) {
            int l = tid + i * 256;
            int r = l >> 3, c = (l & 7) * 4;
            CP_ASYNC16(smaddr(&Ks[r * 36 + c]),
                       kb + (size_t)(it * 128 + r) * KU + c);
        }
    };
    auto prefV = [&](int it, int st) {
        uint32_t* Vs = stg + st * STG + KSZ;
#pragma unroll
        for (int i = 0; i < 4; i++) {
            int l = tid + i * 256;
            int d = l >> 4, c = (l & 15) * 4;
            CP_ASYNC16(smaddr(&Vs[d * 68 + c]),
                       vb + (size_t)d * TU + it * 64 + c);
        }
    };

    // ---------------- Pass 1: row sums ----------------
    float rs0 = 0.f, rs1 = 0.f;
    prefK(0, 0); CP_COMMIT();
    for (int it = 0; it < 16; it++) {
        if (it + 1 < 16) { prefK(it + 1, (it + 1) & 1); CP_COMMIT(); CP_WAIT(1); }
        else { CP_WAIT(0); }
        __syncthreads();
        const uint32_t* Ks = stg + (it & 1) * STG;
#pragma unroll
        for (int nt = 0; nt < 16; nt++) {
            float c4[4] = {0.f, 0.f, 0.f, 0.f};
#pragma unroll
            for (int kt = 0; kt < 4; kt++) {
                uint32_t bf[2];
                int nr = nt * 8 + g;
                bf[0] = Ks[nr * 36 + kt * 8 + t4];
                bf[1] = Ks[nr * 36 + kt * 8 + t4 + 4];
                mma_f16(c4, qf[kt], bf);
            }
            float m0 = msk[it * 128 + nt * 8 + t4 * 2];
            float m1 = msk[it * 128 + nt * 8 + t4 * 2 + 1];
            float e0 = ex2f(fmaf(c4[0], L2E, m0));
            float e1 = ex2f(fmaf(c4[1], L2E, m1));
            float e2 = ex2f(fmaf(c4[2], L2E, m0));
            float e3 = ex2f(fmaf(c4[3], L2E, m1));
            rs0 += e0 + e1;
            rs1 += e2 + e3;
        }
        __syncthreads();
    }
    rs0 += __shfl_xor_sync(0xffffffffu, rs0, 1);
    rs0 += __shfl_xor_sync(0xffffffffu, rs0, 2);
    rs1 += __shfl_xor_sync(0xffffffffu, rs1, 1);
    rs1 += __shfl_xor_sync(0xffffffffu, rs1, 2);
    if (t4 == 0) {
        ILs[warp * 16 + g] = 1.0f / rs0;
        ILs[warp * 16 + g + 8] = 1.0f / rs1;
    }
    __syncthreads();
    const float il0 = ILs[warp * 16 + g];
    const float il1 = ILs[warp * 16 + g + 8];

    // ---------------- Pass 2: p-write + PV ----------------
    float accv[8][4];
#pragma unroll
    for (int dt = 0; dt < 8; dt++)
#pragma unroll
        for (int i = 0; i < 4; i++) accv[dt][i] = 0.f;

    prefK(0, 0); prefV(0, 0); CP_COMMIT();
    for (int it = 0; it < 16; it++) {
        if (it + 1 < 16) {
            prefK(it + 1, (it + 1) & 1); prefV(it + 1, (it + 1) & 1);
            CP_COMMIT(); CP_WAIT(1);
        } else { CP_WAIT(0); }
        __syncthreads();
        const uint32_t* Ks = stg + (it & 1) * STG;
        const uint32_t* Vs = Ks + KSZ;
        uint32_t pf[4];
#pragma unroll
        for (int nt = 0; nt < 16; nt++) {
            float c4[4] = {0.f, 0.f, 0.f, 0.f};
#pragma unroll
            for (int kt = 0; kt < 4; kt++) {
                uint32_t bf[2];
                int nr = nt * 8 + g;
                bf[0] = Ks[nr * 36 + kt * 8 + t4];
                bf[1] = Ks[nr * 36 + kt * 8 + t4 + 4];
                mma_f16(c4, qf[kt], bf);
            }
            float m0 = msk[it * 128 + nt * 8 + t4 * 2];
            float m1 = msk[it * 128 + nt * 8 + t4 * 2 + 1];
            float e0 = ex2f(fmaf(c4[0], L2E, m0));
            float e1 = ex2f(fmaf(c4[1], L2E, m1));
            float e2 = ex2f(fmaf(c4[2], L2E, m0));
            float e3 = ex2f(fmaf(c4[3], L2E, m1));

            if (WRITEP) {
                int row = s0 + warp * 16 + g;
                int col = it * 128 + nt * 8 + t4 * 2;
                float2 p0 = {e0 * il0, e1 * il0};
                float2 p1 = {e2 * il1, e3 * il1};
                *(float2*)(attn_out + ((size_t)bh * SS + row) * SS + col) = p0;
                *(float2*)(attn_out + ((size_t)bh * SS + row + 8) * SS + col) = p1;
            }

            if ((nt & 1) == 0) {
                pf[0] = packh2(e0, e1);
                pf[1] = packh2(e2, e3);
            } else {
                pf[2] = packh2(e0, e1);
                pf[3] = packh2(e2, e3);
                const int ku = (nt >> 1) * 8;   // u32 base of this 16-t chunk
#pragma unroll
                for (int dt = 0; dt < 8; dt++) {
                    uint32_t bf[2];
                    bf[0] = Vs[(dt * 8 + g) * 68 + ku + t4];
                    bf[1] = Vs[(dt * 8 + g) * 68 + ku + t4 + 4];
                    mma_f16(accv[dt], pf, bf);
                }
            }
        }
        __syncthreads();
    }

    // ctx epilogue: scale by invL, store fp16
    {
        int mr = warp * 16 + g;
#pragma unroll
        for (int dt = 0; dt < 8; dt++) {
            uint32_t o0 = packh2(accv[dt][0] * il0, accv[dt][1] * il0);
            uint32_t o1 = packh2(accv[dt][2] * il1, accv[dt][3] * il1);
            ctx[((size_t)b * SS + s0 + mr) * KU + h * 32 + dt * 4 + t4] = o0;
            ctx[((size_t)b * SS + s0 + mr + 8) * KU + h * 32 + dt * 4 + t4] = o1;
        }
    }
}

// ---------------------------------------------------------------------------
extern "C" void kernel_launch(void* const* d_in, const int* in_sizes, int n_in,
                              void* d_out, int out_size)
{
    const float* q    = (const float*)d_in[0];
    const float* k    = (const float*)d_in[1];
    const float* v    = (const float*)d_in[2];
    const float* mask = (const float*)d_in[3];
    const float* wq   = (const float*)d_in[4];
    const float* bq   = (const float*)d_in[5];
    const float* wk   = (const float*)d_in[6];
    const float* bk   = (const float*)d_in[7];
    const float* wv   = (const float*)d_in[8];
    const float* bv   = (const float*)d_in[9];
    const float* wo   = (const float*)d_in[10];
    const float* bo   = (const float*)d_in[11];
    float* out = (float*)d_out;

    uint32_t *qh, *kh, *vh, *wqp, *wkp, *wvp, *wop, *qp, *kp, *vp, *vpt, *ctx;
    cudaGetSymbolAddress((void**)&qh,  g_qh);
    cudaGetSymbolAddress((void**)&kh,  g_kh);
    cudaGetSymbolAddress((void**)&vh,  g_vh);
    cudaGetSymbolAddress((void**)&wqp, g_wqp);
    cudaGetSymbolAddress((void**)&wkp, g_wkp);
    cudaGetSymbolAddress((void**)&wvp, g_wvp);
    cudaGetSymbolAddress((void**)&wop, g_wop);
    cudaGetSymbolAddress((void**)&qp,  g_qp);
    cudaGetSymbolAddress((void**)&kp,  g_kp);
    cudaGetSymbolAddress((void**)&vp,  g_vp);
    cudaGetSymbolAddress((void**)&vpt, g_vpt);
    cudaGetSymbolAddress((void**)&ctx, g_ctx);

    bool attn_in_out = ((size_t)out_size >= OUT_ELEMS + ATTN_ELEMS);
    float* attn_out = attn_in_out ? (out + OUT_ELEMS) : nullptr;

    const int DYN_G = 2 * (128 * 36 + 32 * 136) * 4;                  // 71680
    const int DYN_A = (SS + 128 + 2 * (128 * 36 + 64 * 68)) * 4;      // 80384
    cudaFuncSetAttribute(proj_qkv_tc, cudaFuncAttributeMaxDynamicSharedMemorySize, DYN_G);
    cudaFuncSetAttribute(out_proj_tc, cudaFuncAttributeMaxDynamicSharedMemorySize, DYN_G);
    cudaFuncSetAttribute(attn_fused<true>,  cudaFuncAttributeMaxDynamicSharedMemorySize, DYN_A);
    cudaFuncSetAttribute(attn_fused<false>, cudaFuncAttributeMaxDynamicSharedMemorySize, DYN_A);

    conv_all<<<2048, 256>>>(
        (const float4*)q, (const float4*)k, (const float4*)v,
        wq, wk, wv, wo,
        qh, kh, vh, wqp, wkp, wvp, wop);

    proj_qkv_tc<<<dim3(DD / 128, MROWS / 128, 3), 256, DYN_G>>>(
        qh, kh, vh, wqp, wkp, wvp, bq, bk, bv, qp, kp, vp);

    transpose_v<<<dim3(SS / 64, BB * HH), 256>>>(vp, vpt);

    if (attn_in_out)
        attn_fused<true><<<dim3(SS / 128, BB * HH), 256, DYN_A>>>(
            qp, kp, vpt, mask, attn_out, ctx);
    else
        attn_fused<false><<<dim3(SS / 128, BB * HH), 256, DYN_A>>>(
            qp, kp, vpt, mask, attn_out, ctx);

    out_proj_tc<<<dim3(DD / 128, MROWS / 128), 256, DYN_G>>>(ctx, wop, bo, out);
}

// round 13
// speedup vs baseline: 1.8931x; 1.0069x over previous
#include <cuda_runtime.h>
#include <cuda_fp16.h>
#include <stdint.h>
#include <math.h>

#define BB 2
#define HH 16
#define SS 2048
#define DD 1024
#define DH 64
#define MROWS (BB*SS)          // 4096
#define KU 512                 // u32 (fp16x2) per DD row
#define TU 1024                // u32 (fp16x2) per SS row

static const size_t OUT_ELEMS  = (size_t)BB * SS * DD;        // 4,194,304
static const size_t ATTN_ELEMS = (size_t)BB * HH * SS * SS;   // 134,217,728

// Scratch (__device__ globals)
__device__ uint32_t g_qh[MROWS * KU];
__device__ uint32_t g_kh[MROWS * KU];
__device__ uint32_t g_vh[MROWS * KU];
__device__ uint32_t g_wqp[(DD/2) * DD];
__device__ uint32_t g_wkp[(DD/2) * DD];
__device__ uint32_t g_wvp[(DD/2) * DD];
__device__ uint32_t g_wop[(DD/2) * DD];
__device__ uint32_t g_qp[MROWS * KU];          // pre-scaled by 0.125
__device__ uint32_t g_kp[MROWS * KU];
__device__ uint32_t g_vp[MROWS * KU];
__device__ uint32_t g_vpt[(size_t)BB*HH*DH*TU];
__device__ uint32_t g_ctx[MROWS * KU];

// ---------------------------------------------------------------------------
__device__ __forceinline__ uint32_t packh2(float a, float b) {
    __half2 h = __floats2half2_rn(a, b);
    return *reinterpret_cast<uint32_t*>(&h);
}
__device__ __forceinline__ float ex2f(float x) {
    float y;
    asm("ex2.approx.ftz.f32 %0, %1;" : "=f"(y) : "f"(x));
    return y;
}

__device__ __forceinline__ void mma_f16(float c[4], const uint32_t a[4],
                                        const uint32_t b[2]) {
    asm volatile(
        "mma.sync.aligned.m16n8k16.row.col.f32.f16.f16.f32 "
        "{%0,%1,%2,%3}, {%4,%5,%6,%7}, {%8,%9}, {%0,%1,%2,%3};\n"
        : "+f"(c[0]), "+f"(c[1]), "+f"(c[2]), "+f"(c[3])
        : "r"(a[0]), "r"(a[1]), "r"(a[2]), "r"(a[3]), "r"(b[0]), "r"(b[1]));
}

__device__ __forceinline__ uint32_t smaddr(const void* p) {
    return (uint32_t)__cvta_generic_to_shared(p);
}
// ldmatrix x4: 4 fragment regs from 4 8x8 fp16 matrices (lane-mapped addresses)
__device__ __forceinline__ void ldsm4(uint32_t r[4], const uint32_t* p) {
    uint32_t a = smaddr(p);
    asm volatile(
        "ldmatrix.sync.aligned.m8n8.x4.shared.b16 {%0,%1,%2,%3}, [%4];"
        : "=r"(r[0]), "=r"(r[1]), "=r"(r[2]), "=r"(r[3]) : "r"(a));
}

#define CP_ASYNC16(dst, src) \
    asm volatile("cp.async.cg.shared.global [%0], [%1], 16;" :: "r"(dst), "l"(src))
#define CP_COMMIT() asm volatile("cp.async.commit_group;")
#define CP_WAIT(n)  asm volatile("cp.async.wait_group %0;" :: "n"(n))

// ---------------------------------------------------------------------------
// conv: q,k,v -> fp16; weights -> fp16 packed along k.
// ---------------------------------------------------------------------------
__global__ __launch_bounds__(256) void conv_all(
    const float4* __restrict__ q, const float4* __restrict__ k,
    const float4* __restrict__ v,
    const float* __restrict__ wq, const float* __restrict__ wk,
    const float* __restrict__ wv, const float* __restrict__ wo,
    uint32_t* __restrict__ qh, uint32_t* __restrict__ kh,
    uint32_t* __restrict__ vh,
    uint32_t* __restrict__ wqp, uint32_t* __restrict__ wkp,
    uint32_t* __restrict__ wvp, uint32_t* __restrict__ wop)
{
    const int NQ4 = MROWS * DD / 4;       // 2^20
    const int NW4 = (DD/2) * DD / 4;      // 2^17
    const int TOT = 3 * NQ4 + 4 * NW4;
    for (int i = blockIdx.x * 256 + threadIdx.x; i < TOT; i += gridDim.x * 256) {
        if (i < 3 * NQ4) {
            int s = i >> 20;
            int off = i & (NQ4 - 1);
            const float4* src = (s == 0) ? q : (s == 1) ? k : v;
            uint32_t* dst = (s == 0) ? qh : (s == 1) ? kh : vh;
            float4 x = src[off];
            uint2 u = {packh2(x.x, x.y), packh2(x.z, x.w)};
            *(uint2*)(dst + (size_t)off * 2) = u;
        } else {
            int j = i - 3 * NQ4;
            int s = j >> 17;
            int off = j & (NW4 - 1);
            const float* W = (s == 0) ? wq : (s == 1) ? wk : (s == 2) ? wv : wo;
            uint32_t* dst = (s == 0) ? wqp : (s == 1) ? wkp : (s == 2) ? wvp : wop;
            int kp_ = off >> 8;
            int n4 = (off & 255) * 4;
            float4 a = *(const float4*)(W + (size_t)(2 * kp_) * DD + n4);
            float4 b = *(const float4*)(W + (size_t)(2 * kp_ + 1) * DD + n4);
            uint4 o = {packh2(a.x, b.x), packh2(a.y, b.y),
                       packh2(a.z, b.z), packh2(a.w, b.w)};
            *(uint4*)(dst + (size_t)kp_ * DD + n4) = o;
        }
    }
}

// ---------------------------------------------------------------------------
// fp16 GEMM: C = (A @ W + bias) * alpha. Block 128x128, BK=64, 2-stage.
// ---------------------------------------------------------------------------
template <bool F16OUT>
__device__ __forceinline__ void gemm16_core(
    const uint32_t* __restrict__ A, const uint32_t* __restrict__ Wp,
    const float* __restrict__ bias, void* __restrict__ Cout, float alpha)
{
    extern __shared__ uint32_t dyn[];
    const int AST = 128 * 36;
    const int WST = 32 * 136;
    const int STG = AST + WST;

    const int tid = threadIdx.x;
    const int lane = tid & 31;
    const int warp = tid >> 5;
    const int g = lane >> 2, t4 = lane & 3;
    const int warpM = warp >> 2, warpN = warp & 3;
    const int rowBase = blockIdx.y * 128;
    const int colBase = blockIdx.x * 128;
    const int mOff = warpM * 64, nOff = warpN * 32;

    auto prefetch = [&](int k0u, int s) {
        uint32_t* As = dyn + s * STG;
        uint32_t* Ws = dyn + s * STG + AST;
#pragma unroll
        for (int i = 0; i < 4; i++) {
            int l = tid + i * 256;
            int r = l >> 3, c = (l & 7) * 4;
            CP_ASYNC16(smaddr(&As[r * 36 + c]),
                       A + (size_t)(rowBase + r) * KU + k0u + c);
        }
#pragma unroll
        for (int i = 0; i < 4; i++) {
            int l = tid + i * 256;
            int r = l >> 5, nc = (l & 31) * 4;
            CP_ASYNC16(smaddr(&Ws[r * 136 + nc]),
                       Wp + (size_t)(k0u + r) * DD + colBase + nc);
        }
    };

    float acc[4][4][4];
#pragma unroll
    for (int m = 0; m < 4; m++)
#pragma unroll
        for (int n = 0; n < 4; n++)
#pragma unroll
            for (int i = 0; i < 4; i++) acc[m][n][i] = 0.f;

    prefetch(0, 0);
    CP_COMMIT();

    int stage = 0;
    for (int k0u = 0; k0u < KU; k0u += 32) {
        if (k0u + 32 < KU) {
            prefetch(k0u + 32, stage ^ 1);
            CP_COMMIT();
            CP_WAIT(1);
        } else {
            CP_WAIT(0);
        }
        __syncthreads();

        const uint32_t* As = dyn + stage * STG;
        const uint32_t* Ws = dyn + stage * STG + AST;
#pragma unroll
        for (int ks = 0; ks < 4; ks++) {
            int kb = ks * 8;
            uint32_t af[4][4], bf[4][2];
#pragma unroll
            for (int m = 0; m < 4; m++) {
                int mr = mOff + m * 16 + g;
                af[m][0] = As[mr * 36 + kb + t4];
                af[m][1] = As[(mr + 8) * 36 + kb + t4];
                af[m][2] = As[mr * 36 + kb + t4 + 4];
                af[m][3] = As[(mr + 8) * 36 + kb + t4 + 4];
            }
#pragma unroll
            for (int n = 0; n < 4; n++) {
                int nc = nOff + n * 8 + g;
                bf[n][0] = Ws[(kb + t4) * 136 + nc];
                bf[n][1] = Ws[(kb + t4 + 4) * 136 + nc];
            }
#pragma unroll
            for (int m = 0; m < 4; m++)
#pragma unroll
                for (int n = 0; n < 4; n++) mma_f16(acc[m][n], af[m], bf[n]);
        }
        stage ^= 1;
        __syncthreads();
    }

#pragma unroll
    for (int m = 0; m < 4; m++) {
        int r0 = rowBase + mOff + m * 16 + g;
#pragma unroll
        for (int n = 0; n < 4; n++) {
            int c0 = colBase + nOff + n * 8 + t4 * 2;
            float2 bv = *(const float2*)(bias + c0);
            float v00 = (acc[m][n][0] + bv.x) * alpha;
            float v01 = (acc[m][n][1] + bv.y) * alpha;
            float v10 = (acc[m][n][2] + bv.x) * alpha;
            float v11 = (acc[m][n][3] + bv.y) * alpha;
            if (F16OUT) {
                uint32_t* C = (uint32_t*)Cout;
                C[(size_t)r0 * KU + (c0 >> 1)] = packh2(v00, v01);
                C[(size_t)(r0 + 8) * KU + (c0 >> 1)] = packh2(v10, v11);
            } else {
                float* C = (float*)Cout;
                float2 o0 = {v00, v01}, o1 = {v10, v11};
                *(float2*)(C + (size_t)r0 * DD + c0) = o0;
                *(float2*)(C + (size_t)(r0 + 8) * DD + c0) = o1;
            }
        }
    }
}

__global__ __launch_bounds__(256, 2) void proj_qkv_tc(
    const uint32_t* __restrict__ qh, const uint32_t* __restrict__ kh,
    const uint32_t* __restrict__ vh,
    const uint32_t* __restrict__ wqp, const uint32_t* __restrict__ wkp,
    const uint32_t* __restrict__ wvp,
    const float* __restrict__ bq, const float* __restrict__ bk,
    const float* __restrict__ bv,
    uint32_t* __restrict__ qp, uint32_t* __restrict__ kp,
    uint32_t* __restrict__ vp)
{
    int z = blockIdx.z;
    const uint32_t* A = (z == 0) ? qh : (z == 1) ? kh : vh;
    const uint32_t* W = (z == 0) ? wqp : (z == 1) ? wkp : wvp;
    const float* B    = (z == 0) ? bq : (z == 1) ? bk : bv;
    uint32_t* C       = (z == 0) ? qp : (z == 1) ? kp : vp;
    float alpha       = (z == 0) ? 0.125f : 1.0f;
    gemm16_core<true>(A, W, B, C, alpha);
}

__global__ __launch_bounds__(256, 2) void out_proj_tc(
    const uint32_t* __restrict__ A, const uint32_t* __restrict__ W,
    const float* __restrict__ B, float* __restrict__ C)
{
    gemm16_core<false>(A, W, B, C, 1.0f);
}

// ---------------------------------------------------------------------------
// V head-transpose: vp fp16 [b][t][h*64+d] -> vpt [bh][d][t]
// ---------------------------------------------------------------------------
__global__ __launch_bounds__(256) void transpose_v(
    const uint32_t* __restrict__ vp, uint32_t* __restrict__ vpt)
{
    __shared__ uint16_t Ts[64][66];
    const int tid = threadIdx.x;
    const int bh = blockIdx.y, b = bh >> 4, h = bh & 15;
    const int t0 = blockIdx.x * 64;

#pragma unroll
    for (int i = 0; i < 8; i++) {
        int l = tid + i * 256;
        int r = l >> 5, c = l & 31;
        uint32_t x = vp[(size_t)(b * SS + t0 + r) * KU + h * (DH/2) + c];
        *(uint32_t*)&Ts[r][2 * c] = x;
    }
    __syncthreads();
#pragma unroll
    for (int i = 0; i < 8; i++) {
        int l = tid + i * 256;
        int d = l >> 5, tc = l & 31;
        uint32_t lo = Ts[2 * tc][d];
        uint32_t hi = Ts[2 * tc + 1][d];
        vpt[(size_t)bh * DH * TU + (size_t)d * TU + (t0 >> 1) + tc] =
            lo | (hi << 16);
    }
}

// ---------------------------------------------------------------------------
// Fused attention, two passes over K, ldmatrix fragment loads.
// Dyn smem: msk[2048]f32 + ILs[128]f32 + 2 x (K[128][36] + V[64][68]) u32.
// ---------------------------------------------------------------------------
template <bool WRITEP>
__global__ __launch_bounds__(256, 2) void attn_fused(
    const uint32_t* __restrict__ qp, const uint32_t* __restrict__ kp,
    const uint32_t* __restrict__ vpt, const float* __restrict__ mask,
    float* __restrict__ attn_out, uint32_t* __restrict__ ctx)
{
    extern __shared__ uint32_t dynf[];
    float* msk = (float*)dynf;                 // [2048]
    float* ILs = (float*)(dynf + SS);          // [128]
    uint32_t* stg = dynf + SS + 128;           // 2 stages
    const int KSZ = 128 * 36, VSZ = 64 * 68, STG = KSZ + VSZ;

    const int tid = threadIdx.x;
    const int lane = tid & 31;
    const int warp = tid >> 5;
    const int g = lane >> 2, t4 = lane & 3;
    const int bh = blockIdx.y, b = bh >> 4, h = bh & 15;
    const int s0 = blockIdx.x * 128;
    const float L2E = 1.44269504089f;

    // ldmatrix lane map for B-operands: {r0,r1}=even n-tile, {r2,r3}=odd n-tile
    const int lrowB = ((lane >> 4) & 1) * 8 + (lane & 7);
    const int lcolB = ((lane >> 3) & 1) * 4;

    const uint32_t* qb = qp + (size_t)b * SS * KU + h * 32;
    const uint32_t* kb = kp + (size_t)b * SS * KU + h * 32;
    const uint32_t* vb = vpt + (size_t)bh * DH * TU;

    // mask -> smem, pre-scaled by -1e9*log2e
    for (int i = tid; i < SS; i += 256)
        msk[i] = mask[(size_t)b * SS + i] * (-1e9f * L2E);

    // Q -> stage0 area -> registers (held for whole kernel)
    {
        uint32_t* Qs = stg;
#pragma unroll
        for (int i = 0; i < 4; i++) {
            int l = tid + i * 256;
            int r = l >> 3, c = (l & 7) * 4;
            CP_ASYNC16(smaddr(&Qs[r * 36 + c]), qb + (size_t)(s0 + r) * KU + c);
        }
        CP_COMMIT(); CP_WAIT(0);
        __syncthreads();
    }
    uint32_t qf[4][4];
    {
        const uint32_t* Qs = stg;
        int mr = warp * 16 + g;
#pragma unroll
        for (int kt = 0; kt < 4; kt++) {
            qf[kt][0] = Qs[mr * 36 + kt * 8 + t4];
            qf[kt][1] = Qs[(mr + 8) * 36 + kt * 8 + t4];
            qf[kt][2] = Qs[mr * 36 + kt * 8 + t4 + 4];
            qf[kt][3] = Qs[(mr + 8) * 36 + kt * 8 + t4 + 4];
        }
    }
    __syncthreads();

    auto prefK = [&](int it, int st) {
        uint32_t* Ks = stg + st * STG;
#pragma unroll
        for (int i = 0; i < 4; i++) {
            int l = tid + i * 256;
            int r = l >> 3, c = (l & 7) * 4;
            CP_ASYNC16(smaddr(&Ks[r * 36 + c]),
                       kb + (size_t)(it * 128 + r) * KU + c);
        }
    };
    auto prefV = [&](int it, int st) {
        uint32_t* Vs = stg + st * STG + KSZ;
#pragma unroll
        for (int i = 0; i < 4; i++) {
            int l = tid + i * 256;
            int d = l >> 4, c = (l & 15) * 4;
            CP_ASYNC16(smaddr(&Vs[d * 68 + c]),
                       vb + (size_t)d * TU + it * 64 + c);
        }
    };

    // ---------------- Pass 1: row sums ----------------
    float rs0 = 0.f, rs1 = 0.f;
    prefK(0, 0); CP_COMMIT();
    for (int it = 0; it < 16; it++) {
        if (it + 1 < 16) { prefK(it + 1, (it + 1) & 1); CP_COMMIT(); CP_WAIT(1); }
        else { CP_WAIT(0); }
        __syncthreads();
        const uint32_t* Ks = stg + (it & 1) * STG;
#pragma unroll
        for (int ntp = 0; ntp < 8; ntp++) {
            uint32_t kr[4][4];
#pragma unroll
            for (int kt = 0; kt < 4; kt++)
                ldsm4(kr[kt], Ks + (ntp * 16 + lrowB) * 36 + kt * 8 + lcolB);
            float ca[4] = {0.f, 0.f, 0.f, 0.f};
            float cb[4] = {0.f, 0.f, 0.f, 0.f};
#pragma unroll
            for (int kt = 0; kt < 4; kt++) {
                mma_f16(ca, qf[kt], &kr[kt][0]);
                mma_f16(cb, qf[kt], &kr[kt][2]);
            }
            float m0a = msk[it * 128 + ntp * 16 + t4 * 2];
            float m1a = msk[it * 128 + ntp * 16 + t4 * 2 + 1];
            float m0b = msk[it * 128 + ntp * 16 + 8 + t4 * 2];
            float m1b = msk[it * 128 + ntp * 16 + 8 + t4 * 2 + 1];
            rs0 += ex2f(fmaf(ca[0], L2E, m0a)) + ex2f(fmaf(ca[1], L2E, m1a));
            rs1 += ex2f(fmaf(ca[2], L2E, m0a)) + ex2f(fmaf(ca[3], L2E, m1a));
            rs0 += ex2f(fmaf(cb[0], L2E, m0b)) + ex2f(fmaf(cb[1], L2E, m1b));
            rs1 += ex2f(fmaf(cb[2], L2E, m0b)) + ex2f(fmaf(cb[3], L2E, m1b));
        }
        __syncthreads();
    }
    rs0 += __shfl_xor_sync(0xffffffffu, rs0, 1);
    rs0 += __shfl_xor_sync(0xffffffffu, rs0, 2);
    rs1 += __shfl_xor_sync(0xffffffffu, rs1, 1);
    rs1 += __shfl_xor_sync(0xffffffffu, rs1, 2);
    if (t4 == 0) {
        ILs[warp * 16 + g] = 1.0f / rs0;
        ILs[warp * 16 + g + 8] = 1.0f / rs1;
    }
    __syncthreads();
    const float il0 = ILs[warp * 16 + g];
    const float il1 = ILs[warp * 16 + g + 8];

    // ---------------- Pass 2: p-write + PV ----------------
    float accv[8][4];
#pragma unroll
    for (int dt = 0; dt < 8; dt++)
#pragma unroll
        for (int i = 0; i < 4; i++) accv[dt][i] = 0.f;

    prefK(0, 0); prefV(0, 0); CP_COMMIT();
    for (int it = 0; it < 16; it++) {
        if (it + 1 < 16) {
            prefK(it + 1, (it + 1) & 1); prefV(it + 1, (it + 1) & 1);
            CP_COMMIT(); CP_WAIT(1);
        } else { CP_WAIT(0); }
        __syncthreads();
        const uint32_t* Ks = stg + (it & 1) * STG;
        const uint32_t* Vs = Ks + KSZ;
#pragma unroll
        for (int ntp = 0; ntp < 8; ntp++) {
            uint32_t kr[4][4];
#pragma unroll
            for (int kt = 0; kt < 4; kt++)
                ldsm4(kr[kt], Ks + (ntp * 16 + lrowB) * 36 + kt * 8 + lcolB);
            float ca[4] = {0.f, 0.f, 0.f, 0.f};
            float cb[4] = {0.f, 0.f, 0.f, 0.f};
#pragma unroll
            for (int kt = 0; kt < 4; kt++) {
                mma_f16(ca, qf[kt], &kr[kt][0]);
                mma_f16(cb, qf[kt], &kr[kt][2]);
            }
            float m0a = msk[it * 128 + ntp * 16 + t4 * 2];
            float m1a = msk[it * 128 + ntp * 16 + t4 * 2 + 1];
            float m0b = msk[it * 128 + ntp * 16 + 8 + t4 * 2];
            float m1b = msk[it * 128 + ntp * 16 + 8 + t4 * 2 + 1];
            float e0a = ex2f(fmaf(ca[0], L2E, m0a));
            float e1a = ex2f(fmaf(ca[1], L2E, m1a));
            float e2a = ex2f(fmaf(ca[2], L2E, m0a));
            float e3a = ex2f(fmaf(ca[3], L2E, m1a));
            float e0b = ex2f(fmaf(cb[0], L2E, m0b));
            float e1b = ex2f(fmaf(cb[1], L2E, m1b));
            float e2b = ex2f(fmaf(cb[2], L2E, m0b));
            float e3b = ex2f(fmaf(cb[3], L2E, m1b));

            if (WRITEP) {
                int row = s0 + warp * 16 + g;
                int col = it * 128 + ntp * 16 + t4 * 2;
                float2 p0a = {e0a * il0, e1a * il0};
                float2 p1a = {e2a * il1, e3a * il1};
                float2 p0b = {e0b * il0, e1b * il0};
                float2 p1b = {e2b * il1, e3b * il1};
                float* o0 = attn_out + ((size_t)bh * SS + row) * SS + col;
                float* o1 = attn_out + ((size_t)bh * SS + row + 8) * SS + col;
                *(float2*)o0 = p0a;
                *(float2*)(o0 + 8) = p0b;
                *(float2*)o1 = p1a;
                *(float2*)(o1 + 8) = p1b;
            }

            uint32_t pf[4];
            pf[0] = packh2(e0a, e1a);
            pf[1] = packh2(e2a, e3a);
            pf[2] = packh2(e0b, e1b);
            pf[3] = packh2(e2b, e3b);
            const int ku = ntp * 8;
#pragma unroll
            for (int dp = 0; dp < 4; dp++) {
                uint32_t vr[4];
                ldsm4(vr, Vs + (dp * 16 + lrowB) * 68 + ku + lcolB);
                mma_f16(accv[2 * dp], pf, &vr[0]);
                mma_f16(accv[2 * dp + 1], pf, &vr[2]);
            }
        }
        __syncthreads();
    }

    // ctx epilogue: scale by invL, store fp16
    {
        int mr = warp * 16 + g;
#pragma unroll
        for (int dt = 0; dt < 8; dt++) {
            uint32_t o0 = packh2(accv[dt][0] * il0, accv[dt][1] * il0);
            uint32_t o1 = packh2(accv[dt][2] * il1, accv[dt][3] * il1);
            ctx[((size_t)b * SS + s0 + mr) * KU + h * 32 + dt * 4 + t4] = o0;
            ctx[((size_t)b * SS + s0 + mr + 8) * KU + h * 32 + dt * 4 + t4] = o1;
        }
    }
}

// ---------------------------------------------------------------------------
extern "C" void kernel_launch(void* const* d_in, const int* in_sizes, int n_in,
                              void* d_out, int out_size)
{
    const float* q    = (const float*)d_in[0];
    const float* k    = (const float*)d_in[1];
    const float* v    = (const float*)d_in[2];
    const float* mask = (const float*)d_in[3];
    const float* wq   = (const float*)d_in[4];
    const float* bq   = (const float*)d_in[5];
    const float* wk   = (const float*)d_in[6];
    const float* bk   = (const float*)d_in[7];
    const float* wv   = (const float*)d_in[8];
    const float* bv   = (const float*)d_in[9];
    const float* wo   = (const float*)d_in[10];
    const float* bo   = (const float*)d_in[11];
    float* out = (float*)d_out;

    uint32_t *qh, *kh, *vh, *wqp, *wkp, *wvp, *wop, *qp, *kp, *vp, *vpt, *ctx;
    cudaGetSymbolAddress((void**)&qh,  g_qh);
    cudaGetSymbolAddress((void**)&kh,  g_kh);
    cudaGetSymbolAddress((void**)&vh,  g_vh);
    cudaGetSymbolAddress((void**)&wqp, g_wqp);
    cudaGetSymbolAddress((void**)&wkp, g_wkp);
    cudaGetSymbolAddress((void**)&wvp, g_wvp);
    cudaGetSymbolAddress((void**)&wop, g_wop);
    cudaGetSymbolAddress((void**)&qp,  g_qp);
    cudaGetSymbolAddress((void**)&kp,  g_kp);
    cudaGetSymbolAddress((void**)&vp,  g_vp);
    cudaGetSymbolAddress((void**)&vpt, g_vpt);
    cudaGetSymbolAddress((void**)&ctx, g_ctx);

    bool attn_in_out = ((size_t)out_size >= OUT_ELEMS + ATTN_ELEMS);
    float* attn_out = attn_in_out ? (out + OUT_ELEMS) : nullptr;

    const int DYN_G = 2 * (128 * 36 + 32 * 136) * 4;                  // 71680
    const int DYN_A = (SS + 128 + 2 * (128 * 36 + 64 * 68)) * 4;      // 80384
    cudaFuncSetAttribute(proj_qkv_tc, cudaFuncAttributeMaxDynamicSharedMemorySize, DYN_G);
    cudaFuncSetAttribute(out_proj_tc, cudaFuncAttributeMaxDynamicSharedMemorySize, DYN_G);
    cudaFuncSetAttribute(attn_fused<true>,  cudaFuncAttributeMaxDynamicSharedMemorySize, DYN_A);
    cudaFuncSetAttribute(attn_fused<false>, cudaFuncAttributeMaxDynamicSharedMemorySize, DYN_A);

    conv_all<<<2048, 256>>>(
        (const float4*)q, (const float4*)k, (const float4*)v,
        wq, wk, wv, wo,
        qh, kh, vh, wqp, wkp, wvp, wop);

    proj_qkv_tc<<<dim3(DD / 128, MROWS / 128, 3), 256, DYN_G>>>(
        qh, kh, vh, wqp, wkp, wvp, bq, bk, bv, qp, kp, vp);

    transpose_v<<<dim3(SS / 64, BB * HH), 256>>>(vp, vpt);

    if (attn_in_out)
        attn_fused<true><<<dim3(SS / 128, BB * HH), 256, DYN_A>>>(
            qp, kp, vpt, mask, attn_out, ctx);
    else
        attn_fused<false><<<dim3(SS / 128, BB * HH), 256, DYN_A>>>(
            qp, kp, vpt, mask, attn_out, ctx);

    out_proj_tc<<<dim3(DD / 128, MROWS / 128), 256, DYN_G>>>(ctx, wop, bo, out);
}

// round 14
// speedup vs baseline: 2.1321x; 1.1263x over previous
#include <cuda_runtime.h>
#include <cuda_fp16.h>
#include <stdint.h>
#include <math.h>

#define BB 2
#define HH 16
#define SS 2048
#define DD 1024
#define DH 64
#define MROWS (BB*SS)          // 4096
#define KU 512                 // u32 (fp16x2) per DD row
#define TU 1024                // u32 (fp16x2) per SS row

static const size_t OUT_ELEMS  = (size_t)BB * SS * DD;        // 4,194,304
static const size_t ATTN_ELEMS = (size_t)BB * HH * SS * SS;   // 134,217,728

// Scratch (__device__ globals)
__device__ uint32_t g_qh[MROWS * KU];
__device__ uint32_t g_kh[MROWS * KU];
__device__ uint32_t g_vh[MROWS * KU];
__device__ uint32_t g_wqp[(DD/2) * DD];
__device__ uint32_t g_wkp[(DD/2) * DD];
__device__ uint32_t g_wvp[(DD/2) * DD];
__device__ uint32_t g_wop[(DD/2) * DD];
__device__ uint32_t g_qp[MROWS * KU];          // pre-scaled by 0.125
__device__ uint32_t g_kp[MROWS * KU];
__device__ uint32_t g_vp[MROWS * KU];
__device__ uint32_t g_vpt[(size_t)BB*HH*DH*TU];
__device__ uint32_t g_ctx[MROWS * KU];

// ---------------------------------------------------------------------------
__device__ __forceinline__ uint32_t packh2(float a, float b) {
    __half2 h = __floats2half2_rn(a, b);
    return *reinterpret_cast<uint32_t*>(&h);
}
__device__ __forceinline__ float ex2f(float x) {
    float y;
    asm("ex2.approx.ftz.f32 %0, %1;" : "=f"(y) : "f"(x));
    return y;
}

__device__ __forceinline__ void mma_f16(float c[4], const uint32_t a[4],
                                        const uint32_t b[2]) {
    asm volatile(
        "mma.sync.aligned.m16n8k16.row.col.f32.f16.f16.f32 "
        "{%0,%1,%2,%3}, {%4,%5,%6,%7}, {%8,%9}, {%0,%1,%2,%3};\n"
        : "+f"(c[0]), "+f"(c[1]), "+f"(c[2]), "+f"(c[3])
        : "r"(a[0]), "r"(a[1]), "r"(a[2]), "r"(a[3]), "r"(b[0]), "r"(b[1]));
}

__device__ __forceinline__ uint32_t smaddr(const void* p) {
    return (uint32_t)__cvta_generic_to_shared(p);
}
__device__ __forceinline__ void ldsm4(uint32_t r[4], const uint32_t* p) {
    uint32_t a = smaddr(p);
    asm volatile(
        "ldmatrix.sync.aligned.m8n8.x4.shared.b16 {%0,%1,%2,%3}, [%4];"
        : "=r"(r[0]), "=r"(r[1]), "=r"(r[2]), "=r"(r[3]) : "r"(a));
}

#define CP_ASYNC16(dst, src) \
    asm volatile("cp.async.cg.shared.global [%0], [%1], 16;" :: "r"(dst), "l"(src))
#define CP_COMMIT() asm volatile("cp.async.commit_group;")
#define CP_WAIT(n)  asm volatile("cp.async.wait_group %0;" :: "n"(n))

// ---------------------------------------------------------------------------
// conv: q,k,v -> fp16; weights -> fp16 packed along k.
// ---------------------------------------------------------------------------
__global__ __launch_bounds__(256) void conv_all(
    const float4* __restrict__ q, const float4* __restrict__ k,
    const float4* __restrict__ v,
    const float* __restrict__ wq, const float* __restrict__ wk,
    const float* __restrict__ wv, const float* __restrict__ wo,
    uint32_t* __restrict__ qh, uint32_t* __restrict__ kh,
    uint32_t* __restrict__ vh,
    uint32_t* __restrict__ wqp, uint32_t* __restrict__ wkp,
    uint32_t* __restrict__ wvp, uint32_t* __restrict__ wop)
{
    const int NQ4 = MROWS * DD / 4;       // 2^20
    const int NW4 = (DD/2) * DD / 4;      // 2^17
    const int TOT = 3 * NQ4 + 4 * NW4;
    for (int i = blockIdx.x * 256 + threadIdx.x; i < TOT; i += gridDim.x * 256) {
        if (i < 3 * NQ4) {
            int s = i >> 20;
            int off = i & (NQ4 - 1);
            const float4* src = (s == 0) ? q : (s == 1) ? k : v;
            uint32_t* dst = (s == 0) ? qh : (s == 1) ? kh : vh;
            float4 x = src[off];
            uint2 u = {packh2(x.x, x.y), packh2(x.z, x.w)};
            *(uint2*)(dst + (size_t)off * 2) = u;
        } else {
            int j = i - 3 * NQ4;
            int s = j >> 17;
            int off = j & (NW4 - 1);
            const float* W = (s == 0) ? wq : (s == 1) ? wk : (s == 2) ? wv : wo;
            uint32_t* dst = (s == 0) ? wqp : (s == 1) ? wkp : (s == 2) ? wvp : wop;
            int kp_ = off >> 8;
            int n4 = (off & 255) * 4;
            float4 a = *(const float4*)(W + (size_t)(2 * kp_) * DD + n4);
            float4 b = *(const float4*)(W + (size_t)(2 * kp_ + 1) * DD + n4);
            uint4 o = {packh2(a.x, b.x), packh2(a.y, b.y),
                       packh2(a.z, b.z), packh2(a.w, b.w)};
            *(uint4*)(dst + (size_t)kp_ * DD + n4) = o;
        }
    }
}

// ---------------------------------------------------------------------------
// fp16 GEMM: C = (A @ W + bias) * alpha. Block 128x128, BK=64, 2-stage.
// ---------------------------------------------------------------------------
template <bool F16OUT>
__device__ __forceinline__ void gemm16_core(
    const uint32_t* __restrict__ A, const uint32_t* __restrict__ Wp,
    const float* __restrict__ bias, void* __restrict__ Cout, float alpha)
{
    extern __shared__ uint32_t dyn[];
    const int AST = 128 * 36;
    const int WST = 32 * 136;
    const int STG = AST + WST;

    const int tid = threadIdx.x;
    const int lane = tid & 31;
    const int warp = tid >> 5;
    const int g = lane >> 2, t4 = lane & 3;
    const int warpM = warp >> 2, warpN = warp & 3;
    const int rowBase = blockIdx.y * 128;
    const int colBase = blockIdx.x * 128;
    const int mOff = warpM * 64, nOff = warpN * 32;

    auto prefetch = [&](int k0u, int s) {
        uint32_t* As = dyn + s * STG;
        uint32_t* Ws = dyn + s * STG + AST;
#pragma unroll
        for (int i = 0; i < 4; i++) {
            int l = tid + i * 256;
            int r = l >> 3, c = (l & 7) * 4;
            CP_ASYNC16(smaddr(&As[r * 36 + c]),
                       A + (size_t)(rowBase + r) * KU + k0u + c);
        }
#pragma unroll
        for (int i = 0; i < 4; i++) {
            int l = tid + i * 256;
            int r = l >> 5, nc = (l & 31) * 4;
            CP_ASYNC16(smaddr(&Ws[r * 136 + nc]),
                       Wp + (size_t)(k0u + r) * DD + colBase + nc);
        }
    };

    float acc[4][4][4];
#pragma unroll
    for (int m = 0; m < 4; m++)
#pragma unroll
        for (int n = 0; n < 4; n++)
#pragma unroll
            for (int i = 0; i < 4; i++) acc[m][n][i] = 0.f;

    prefetch(0, 0);
    CP_COMMIT();

    int stage = 0;
    for (int k0u = 0; k0u < KU; k0u += 32) {
        if (k0u + 32 < KU) {
            prefetch(k0u + 32, stage ^ 1);
            CP_COMMIT();
            CP_WAIT(1);
        } else {
            CP_WAIT(0);
        }
        __syncthreads();

        const uint32_t* As = dyn + stage * STG;
        const uint32_t* Ws = dyn + stage * STG + AST;
#pragma unroll
        for (int ks = 0; ks < 4; ks++) {
            int kb = ks * 8;
            uint32_t af[4][4], bf[4][2];
#pragma unroll
            for (int m = 0; m < 4; m++) {
                int mr = mOff + m * 16 + g;
                af[m][0] = As[mr * 36 + kb + t4];
                af[m][1] = As[(mr + 8) * 36 + kb + t4];
                af[m][2] = As[mr * 36 + kb + t4 + 4];
                af[m][3] = As[(mr + 8) * 36 + kb + t4 + 4];
            }
#pragma unroll
            for (int n = 0; n < 4; n++) {
                int nc = nOff + n * 8 + g;
                bf[n][0] = Ws[(kb + t4) * 136 + nc];
                bf[n][1] = Ws[(kb + t4 + 4) * 136 + nc];
            }
#pragma unroll
            for (int m = 0; m < 4; m++)
#pragma unroll
                for (int n = 0; n < 4; n++) mma_f16(acc[m][n], af[m], bf[n]);
        }
        stage ^= 1;
        __syncthreads();
    }

#pragma unroll
    for (int m = 0; m < 4; m++) {
        int r0 = rowBase + mOff + m * 16 + g;
#pragma unroll
        for (int n = 0; n < 4; n++) {
            int c0 = colBase + nOff + n * 8 + t4 * 2;
            float2 bv = *(const float2*)(bias + c0);
            float v00 = (acc[m][n][0] + bv.x) * alpha;
            float v01 = (acc[m][n][1] + bv.y) * alpha;
            float v10 = (acc[m][n][2] + bv.x) * alpha;
            float v11 = (acc[m][n][3] + bv.y) * alpha;
            if (F16OUT) {
                uint32_t* C = (uint32_t*)Cout;
                C[(size_t)r0 * KU + (c0 >> 1)] = packh2(v00, v01);
                C[(size_t)(r0 + 8) * KU + (c0 >> 1)] = packh2(v10, v11);
            } else {
                float* C = (float*)Cout;
                float2 o0 = {v00, v01}, o1 = {v10, v11};
                *(float2*)(C + (size_t)r0 * DD + c0) = o0;
                *(float2*)(C + (size_t)(r0 + 8) * DD + c0) = o1;
            }
        }
    }
}

__global__ __launch_bounds__(256, 2) void proj_qkv_tc(
    const uint32_t* __restrict__ qh, const uint32_t* __restrict__ kh,
    const uint32_t* __restrict__ vh,
    const uint32_t* __restrict__ wqp, const uint32_t* __restrict__ wkp,
    const uint32_t* __restrict__ wvp,
    const float* __restrict__ bq, const float* __restrict__ bk,
    const float* __restrict__ bv,
    uint32_t* __restrict__ qp, uint32_t* __restrict__ kp,
    uint32_t* __restrict__ vp)
{
    int z = blockIdx.z;
    const uint32_t* A = (z == 0) ? qh : (z == 1) ? kh : vh;
    const uint32_t* W = (z == 0) ? wqp : (z == 1) ? wkp : wvp;
    const float* B    = (z == 0) ? bq : (z == 1) ? bk : bv;
    uint32_t* C       = (z == 0) ? qp : (z == 1) ? kp : vp;
    float alpha       = (z == 0) ? 0.125f : 1.0f;
    gemm16_core<true>(A, W, B, C, alpha);
}

__global__ __launch_bounds__(256, 2) void out_proj_tc(
    const uint32_t* __restrict__ A, const uint32_t* __restrict__ W,
    const float* __restrict__ B, float* __restrict__ C)
{
    gemm16_core<false>(A, W, B, C, 1.0f);
}

// ---------------------------------------------------------------------------
// V head-transpose: vp fp16 [b][t][h*64+d] -> vpt [bh][d][t]
// ---------------------------------------------------------------------------
__global__ __launch_bounds__(256) void transpose_v(
    const uint32_t* __restrict__ vp, uint32_t* __restrict__ vpt)
{
    __shared__ uint16_t Ts[64][66];
    const int tid = threadIdx.x;
    const int bh = blockIdx.y, b = bh >> 4, h = bh & 15;
    const int t0 = blockIdx.x * 64;

#pragma unroll
    for (int i = 0; i < 8; i++) {
        int l = tid + i * 256;
        int r = l >> 5, c = l & 31;
        uint32_t x = vp[(size_t)(b * SS + t0 + r) * KU + h * (DH/2) + c];
        *(uint32_t*)&Ts[r][2 * c] = x;
    }
    __syncthreads();
#pragma unroll
    for (int i = 0; i < 8; i++) {
        int l = tid + i * 256;
        int d = l >> 5, tc = l & 31;
        uint32_t lo = Ts[2 * tc][d];
        uint32_t hi = Ts[2 * tc + 1][d];
        vpt[(size_t)bh * DH * TU + (size_t)d * TU + (t0 >> 1) + tc] =
            lo | (hi << 16);
    }
}

// ---------------------------------------------------------------------------
// Fused attention: 128 threads, 4 warps x 32 s-rows (two m16 tiles each).
// Two passes over K in 64-row chunks (32 iters/pass), 2-stage cp.async.
// Halved K/V fragment smem traffic vs 8-warp layout.
// Dyn smem: msk fp16[2048] + ILs f32[128] + 2 x (K[64][36]+V[64][36]) u32
//         = 41472 B. __launch_bounds__(128,3).
// ---------------------------------------------------------------------------
template <bool WRITEP>
__global__ __launch_bounds__(128, 3) void attn_fused(
    const uint32_t* __restrict__ qp, const uint32_t* __restrict__ kp,
    const uint32_t* __restrict__ vpt, const float* __restrict__ mask,
    float* __restrict__ attn_out, uint32_t* __restrict__ ctx)
{
    extern __shared__ uint32_t dynf[];
    uint32_t* mskU = dynf;                 // [1024] u32 = 2048 fp16
    float* ILs = (float*)(dynf + 1024);    // [128]
    uint32_t* stg = dynf + 1024 + 128;
    const int KSZ = 64 * 36, STG = 2 * KSZ;   // K[64][36] + V[64][36]

    const int tid = threadIdx.x;
    const int lane = tid & 31;
    const int warp = tid >> 5;             // 0..3
    const int g = lane >> 2, t4 = lane & 3;
    const int bh = blockIdx.y, b = bh >> 4, h = bh & 15;
    const int s0 = blockIdx.x * 128;
    const float L2E = 1.44269504089f;

    const int lrowB = ((lane >> 4) & 1) * 8 + (lane & 7);
    const int lcolB = ((lane >> 3) & 1) * 4;

    const uint32_t* qb = qp + (size_t)b * SS * KU + h * 32;
    const uint32_t* kb = kp + (size_t)b * SS * KU + h * 32;
    const uint32_t* vb = vpt + (size_t)bh * DH * TU;

    // mask -> smem as clamped fp16 pairs (pre-scaled by -1e9*log2e)
    for (int i = tid; i < 1024; i += 128) {
        float2 mv = *(const float2*)(mask + (size_t)b * SS + 2 * i);
        float a = fmaxf(mv.x * (-1e9f * L2E), -60000.f);
        float c = fmaxf(mv.y * (-1e9f * L2E), -60000.f);
        mskU[i] = packh2(a, c);
    }

    // Q -> stage area -> registers (held for whole kernel)
    {
        uint32_t* Qs = stg;                // 128 x 36 = 4608 u32 (fits 2 stages)
#pragma unroll
        for (int i = 0; i < 8; i++) {
            int l = tid + i * 128;
            int r = l >> 3, c = (l & 7) * 4;
            CP_ASYNC16(smaddr(&Qs[r * 36 + c]), qb + (size_t)(s0 + r) * KU + c);
        }
        CP_COMMIT(); CP_WAIT(0);
        __syncthreads();
    }
    uint32_t qf[2][4][4];
    {
        const uint32_t* Qs = stg;
#pragma unroll
        for (int m = 0; m < 2; m++) {
            int mr = warp * 32 + m * 16 + g;
#pragma unroll
            for (int kt = 0; kt < 4; kt++) {
                qf[m][kt][0] = Qs[mr * 36 + kt * 8 + t4];
                qf[m][kt][1] = Qs[(mr + 8) * 36 + kt * 8 + t4];
                qf[m][kt][2] = Qs[mr * 36 + kt * 8 + t4 + 4];
                qf[m][kt][3] = Qs[(mr + 8) * 36 + kt * 8 + t4 + 4];
            }
        }
    }
    __syncthreads();

    auto prefK = [&](int it, int st) {
        uint32_t* Ks = stg + st * STG;
#pragma unroll
        for (int i = 0; i < 4; i++) {
            int l = tid + i * 128;
            int r = l >> 3, c = (l & 7) * 4;
            CP_ASYNC16(smaddr(&Ks[r * 36 + c]),
                       kb + (size_t)(it * 64 + r) * KU + c);
        }
    };
    auto prefV = [&](int it, int st) {
        uint32_t* Vs = stg + st * STG + KSZ;
#pragma unroll
        for (int i = 0; i < 4; i++) {
            int l = tid + i * 128;
            int d = l >> 3, c = (l & 7) * 4;
            CP_ASYNC16(smaddr(&Vs[d * 36 + c]),
                       vb + (size_t)d * TU + it * 32 + c);
        }
    };

    // ---------------- Pass 1: row sums ----------------
    float rs[2][2] = {{0.f, 0.f}, {0.f, 0.f}};
    prefK(0, 0); CP_COMMIT();
    for (int it = 0; it < 32; it++) {
        if (it + 1 < 32) { prefK(it + 1, (it + 1) & 1); CP_COMMIT(); CP_WAIT(1); }
        else { CP_WAIT(0); }
        __syncthreads();
        const uint32_t* Ks = stg + (it & 1) * STG;
#pragma unroll
        for (int ntp = 0; ntp < 4; ntp++) {
            uint32_t kr[4][4];
#pragma unroll
            for (int kt = 0; kt < 4; kt++)
                ldsm4(kr[kt], Ks + (ntp * 16 + lrowB) * 36 + kt * 8 + lcolB);
            uint32_t mua = mskU[it * 32 + ntp * 8 + t4];
            uint32_t mub = mskU[it * 32 + ntp * 8 + 4 + t4];
            float2 mka = __half22float2(*(__half2*)&mua);
            float2 mkb = __half22float2(*(__half2*)&mub);
#pragma unroll
            for (int m = 0; m < 2; m++) {
                float ca[4] = {0.f, 0.f, 0.f, 0.f};
                float cb[4] = {0.f, 0.f, 0.f, 0.f};
#pragma unroll
                for (int kt = 0; kt < 4; kt++) {
                    mma_f16(ca, qf[m][kt], &kr[kt][0]);
                    mma_f16(cb, qf[m][kt], &kr[kt][2]);
                }
                rs[m][0] += ex2f(fmaf(ca[0], L2E, mka.x))
                          + ex2f(fmaf(ca[1], L2E, mka.y))
                          + ex2f(fmaf(cb[0], L2E, mkb.x))
                          + ex2f(fmaf(cb[1], L2E, mkb.y));
                rs[m][1] += ex2f(fmaf(ca[2], L2E, mka.x))
                          + ex2f(fmaf(ca[3], L2E, mka.y))
                          + ex2f(fmaf(cb[2], L2E, mkb.x))
                          + ex2f(fmaf(cb[3], L2E, mkb.y));
            }
        }
        __syncthreads();
    }
#pragma unroll
    for (int m = 0; m < 2; m++)
#pragma unroll
        for (int hh = 0; hh < 2; hh++) {
            float s = rs[m][hh];
            s += __shfl_xor_sync(0xffffffffu, s, 1);
            s += __shfl_xor_sync(0xffffffffu, s, 2);
            if (t4 == 0) ILs[warp * 32 + m * 16 + g + hh * 8] = 1.0f / s;
        }
    __syncthreads();
    float il[2][2];
#pragma unroll
    for (int m = 0; m < 2; m++) {
        il[m][0] = ILs[warp * 32 + m * 16 + g];
        il[m][1] = ILs[warp * 32 + m * 16 + g + 8];
    }

    // ---------------- Pass 2: p-write + PV ----------------
    float accv[2][8][4];
#pragma unroll
    for (int m = 0; m < 2; m++)
#pragma unroll
        for (int dt = 0; dt < 8; dt++)
#pragma unroll
            for (int i = 0; i < 4; i++) accv[m][dt][i] = 0.f;

    prefK(0, 0); prefV(0, 0); CP_COMMIT();
    for (int it = 0; it < 32; it++) {
        if (it + 1 < 32) {
            prefK(it + 1, (it + 1) & 1); prefV(it + 1, (it + 1) & 1);
            CP_COMMIT(); CP_WAIT(1);
        } else { CP_WAIT(0); }
        __syncthreads();
        const uint32_t* Ks = stg + (it & 1) * STG;
        const uint32_t* Vs = Ks + KSZ;
#pragma unroll
        for (int ntp = 0; ntp < 4; ntp++) {
            uint32_t kr[4][4];
#pragma unroll
            for (int kt = 0; kt < 4; kt++)
                ldsm4(kr[kt], Ks + (ntp * 16 + lrowB) * 36 + kt * 8 + lcolB);
            uint32_t mua = mskU[it * 32 + ntp * 8 + t4];
            uint32_t mub = mskU[it * 32 + ntp * 8 + 4 + t4];
            float2 mka = __half22float2(*(__half2*)&mua);
            float2 mkb = __half22float2(*(__half2*)&mub);

            uint32_t pf[2][4];
#pragma unroll
            for (int m = 0; m < 2; m++) {
                float ca[4] = {0.f, 0.f, 0.f, 0.f};
                float cb[4] = {0.f, 0.f, 0.f, 0.f};
#pragma unroll
                for (int kt = 0; kt < 4; kt++) {
                    mma_f16(ca, qf[m][kt], &kr[kt][0]);
                    mma_f16(cb, qf[m][kt], &kr[kt][2]);
                }
                float e0a = ex2f(fmaf(ca[0], L2E, mka.x));
                float e1a = ex2f(fmaf(ca[1], L2E, mka.y));
                float e2a = ex2f(fmaf(ca[2], L2E, mka.x));
                float e3a = ex2f(fmaf(ca[3], L2E, mka.y));
                float e0b = ex2f(fmaf(cb[0], L2E, mkb.x));
                float e1b = ex2f(fmaf(cb[1], L2E, mkb.y));
                float e2b = ex2f(fmaf(cb[2], L2E, mkb.x));
                float e3b = ex2f(fmaf(cb[3], L2E, mkb.y));

                if (WRITEP) {
                    int row = s0 + warp * 32 + m * 16 + g;
                    int col = it * 64 + ntp * 16 + t4 * 2;
                    float2 p0a = {e0a * il[m][0], e1a * il[m][0]};
                    float2 p1a = {e2a * il[m][1], e3a * il[m][1]};
                    float2 p0b = {e0b * il[m][0], e1b * il[m][0]};
                    float2 p1b = {e2b * il[m][1], e3b * il[m][1]};
                    float* o0 = attn_out + ((size_t)bh * SS + row) * SS + col;
                    float* o1 = attn_out + ((size_t)bh * SS + row + 8) * SS + col;
                    *(float2*)o0 = p0a;
                    *(float2*)(o0 + 8) = p0b;
                    *(float2*)o1 = p1a;
                    *(float2*)(o1 + 8) = p1b;
                }

                pf[m][0] = packh2(e0a, e1a);
                pf[m][1] = packh2(e2a, e3a);
                pf[m][2] = packh2(e0b, e1b);
                pf[m][3] = packh2(e2b, e3b);
            }

            const int ku = ntp * 8;
#pragma unroll
            for (int dp = 0; dp < 4; dp++) {
                uint32_t vr[4];
                ldsm4(vr, Vs + (dp * 16 + lrowB) * 36 + ku + lcolB);
#pragma unroll
                for (int m = 0; m < 2; m++) {
                    mma_f16(accv[m][2 * dp], pf[m], &vr[0]);
                    mma_f16(accv[m][2 * dp + 1], pf[m], &vr[2]);
                }
            }
        }
        __syncthreads();
    }

    // ctx epilogue: scale by invL, store fp16
#pragma unroll
    for (int m = 0; m < 2; m++) {
        int mr = warp * 32 + m * 16 + g;
#pragma unroll
        for (int dt = 0; dt < 8; dt++) {
            uint32_t o0 = packh2(accv[m][dt][0] * il[m][0],
                                 accv[m][dt][1] * il[m][0]);
            uint32_t o1 = packh2(accv[m][dt][2] * il[m][1],
                                 accv[m][dt][3] * il[m][1]);
            ctx[((size_t)b * SS + s0 + mr) * KU + h * 32 + dt * 4 + t4] = o0;
            ctx[((size_t)b * SS + s0 + mr + 8) * KU + h * 32 + dt * 4 + t4] = o1;
        }
    }
}

// ---------------------------------------------------------------------------
extern "C" void kernel_launch(void* const* d_in, const int* in_sizes, int n_in,
                              void* d_out, int out_size)
{
    const float* q    = (const float*)d_in[0];
    const float* k    = (const float*)d_in[1];
    const float* v    = (const float*)d_in[2];
    const float* mask = (const float*)d_in[3];
    const float* wq   = (const float*)d_in[4];
    const float* bq   = (const float*)d_in[5];
    const float* wk   = (const float*)d_in[6];
    const float* bk   = (const float*)d_in[7];
    const float* wv   = (const float*)d_in[8];
    const float* bv   = (const float*)d_in[9];
    const float* wo   = (const float*)d_in[10];
    const float* bo   = (const float*)d_in[11];
    float* out = (float*)d_out;

    uint32_t *qh, *kh, *vh, *wqp, *wkp, *wvp, *wop, *qp, *kp, *vp, *vpt, *ctx;
    cudaGetSymbolAddress((void**)&qh,  g_qh);
    cudaGetSymbolAddress((void**)&kh,  g_kh);
    cudaGetSymbolAddress((void**)&vh,  g_vh);
    cudaGetSymbolAddress((void**)&wqp, g_wqp);
    cudaGetSymbolAddress((void**)&wkp, g_wkp);
    cudaGetSymbolAddress((void**)&wvp, g_wvp);
    cudaGetSymbolAddress((void**)&wop, g_wop);
    cudaGetSymbolAddress((void**)&qp,  g_qp);
    cudaGetSymbolAddress((void**)&kp,  g_kp);
    cudaGetSymbolAddress((void**)&vp,  g_vp);
    cudaGetSymbolAddress((void**)&vpt, g_vpt);
    cudaGetSymbolAddress((void**)&ctx, g_ctx);

    bool attn_in_out = ((size_t)out_size >= OUT_ELEMS + ATTN_ELEMS);
    float* attn_out = attn_in_out ? (out + OUT_ELEMS) : nullptr;

    const int DYN_G = 2 * (128 * 36 + 32 * 136) * 4;       // 71680
    const int DYN_A = (1024 + 128 + 2 * (64 * 36 * 2)) * 4; // 41472
    cudaFuncSetAttribute(proj_qkv_tc, cudaFuncAttributeMaxDynamicSharedMemorySize, DYN_G);
    cudaFuncSetAttribute(out_proj_tc, cudaFuncAttributeMaxDynamicSharedMemorySize, DYN_G);
    cudaFuncSetAttribute(attn_fused<true>,  cudaFuncAttributeMaxDynamicSharedMemorySize, DYN_A);
    cudaFuncSetAttribute(attn_fused<false>, cudaFuncAttributeMaxDynamicSharedMemorySize, DYN_A);

    conv_all<<<2048, 256>>>(
        (const float4*)q, (const float4*)k, (const float4*)v,
        wq, wk, wv, wo,
        qh, kh, vh, wqp, wkp, wvp, wop);

    proj_qkv_tc<<<dim3(DD / 128, MROWS / 128, 3), 256, DYN_G>>>(
        qh, kh, vh, wqp, wkp, wvp, bq, bk, bv, qp, kp, vp);

    transpose_v<<<dim3(SS / 64, BB * HH), 256>>>(vp, vpt);

    if (attn_in_out)
        attn_fused<true><<<dim3(SS / 128, BB * HH), 128, DYN_A>>>(
            qp, kp, vpt, mask, attn_out, ctx);
    else
        attn_fused<false><<<dim3(SS / 128, BB * HH), 128, DYN_A>>>(
            qp, kp, vpt, mask, attn_out, ctx);

    out_proj_tc<<<dim3(DD / 128, MROWS / 128), 256, DYN_G>>>(ctx, wop, bo, out);
}